// round 15
// baseline (speedup 1.0000x reference)
#include <cuda_runtime.h>
#include <cuda_bf16.h>
#include <cuda_fp16.h>
#include <cstdint>
#include <cstddef>

// Problem constants
#define Bb 4
#define Tt 2048
#define Cc 2048
#define Hh 32
#define Kk 64
#define Mm (Bb*Tt)          // 8192
#define EPSV 0.00064f

// ---------------- scratch (device globals; no allocation allowed) ----------
__device__ __align__(256) __nv_bfloat16 g_AH[(size_t)4*Mm*Cc];
__device__ __align__(256) __nv_bfloat16 g_AL[(size_t)3*Mm*Cc];
__device__ __align__(256) __nv_bfloat16 g_WH[(size_t)5*Cc*Cc];
__device__ __align__(256) __nv_bfloat16 g_WL[(size_t)3*Cc*Cc];
__device__ __align__(256) __nv_bfloat16 g_YH[(size_t)Mm*Cc];   // fp16 payload
__device__ float g_R[(size_t)Mm*Cc];
__device__ float g_Kb[(size_t)Mm*Cc];
__device__ float g_V[(size_t)Mm*Cc];
__device__ float g_G[(size_t)Mm*Cc];
__device__ float g_WKV[(size_t)Mm*Cc];   // base term
__device__ float g_IN[(size_t)Mm*Cc];    // intra term (t>=1 valid)

// ---------------- helpers ----------------------------------------------------
__device__ __forceinline__ uint32_t smem_u32(const void* p) {
    uint32_t a;
    asm("{ .reg .u64 t; cvta.to.shared.u64 t, %1; cvt.u32.u64 %0, t; }"
        : "=r"(a) : "l"(p));
    return a;
}
#define CP16(dst, src) \
    asm volatile("cp.async.cg.shared.global [%0], [%1], 16;" :: "r"(dst), "l"(src))
#define CP_COMMIT() asm volatile("cp.async.commit_group;" ::: "memory")

__device__ __forceinline__ void ldsm4(uint32_t* r, uint32_t addr) {
    asm volatile("ldmatrix.sync.aligned.m8n8.x4.shared.b16 {%0,%1,%2,%3}, [%4];"
                 : "=r"(r[0]), "=r"(r[1]), "=r"(r[2]), "=r"(r[3]) : "r"(addr));
}
__device__ __forceinline__ void mma_bf16(float* c, const uint32_t* a,
                                         const uint32_t* b) {
    asm volatile(
        "mma.sync.aligned.m16n8k16.row.col.f32.bf16.bf16.f32 "
        "{%0,%1,%2,%3}, {%4,%5,%6,%7}, {%8,%9}, {%0,%1,%2,%3};"
        : "+f"(c[0]), "+f"(c[1]), "+f"(c[2]), "+f"(c[3])
        : "r"(a[0]), "r"(a[1]), "r"(a[2]), "r"(a[3]), "r"(b[0]), "r"(b[1]));
}
__device__ __forceinline__ void mma_fp16(float* c, const uint32_t* a,
                                         const uint32_t* b) {
    asm volatile(
        "mma.sync.aligned.m16n8k16.row.col.f32.f16.f16.f32 "
        "{%0,%1,%2,%3}, {%4,%5,%6,%7}, {%8,%9}, {%0,%1,%2,%3};"
        : "+f"(c[0]), "+f"(c[1]), "+f"(c[2]), "+f"(c[3])
        : "r"(a[0]), "r"(a[1]), "r"(a[2]), "r"(a[3]), "r"(b[0]), "r"(b[1]));
}
__device__ __forceinline__ void split2(float a, __nv_bfloat16& h, __nv_bfloat16& l) {
    h = __float2bfloat16(a);
    l = __float2bfloat16(a - __bfloat162float(h));
}

// ---------------- conversion kernels ----------------------------------------
__global__ __launch_bounds__(256) void mixconv_kernel(
    const float* __restrict__ x, const float* __restrict__ state,
    const float* __restrict__ tmr, const float* __restrict__ tmk,
    const float* __restrict__ tmv, const float* __restrict__ tmg)
{
    const size_t idx = (size_t)blockIdx.x * 256 + threadIdx.x;   // over M*C/4
    const int m = (int)(idx >> 9);
    const int c = ((int)idx & 511) << 2;
    const int t = m & (Tt - 1);

    float4 xv = *(const float4*)(x + (size_t)m * Cc + c);
    float4 pv = (t == 0) ? *(const float4*)(state + c)
                         : *(const float4*)(x + (size_t)(m - 1) * Cc + c);
    const float* tms[4] = {tmr, tmk, tmv, tmg};
    #pragma unroll
    for (int mix = 0; mix < 4; mix++) {
        float4 tv = *(const float4*)(tms[mix] + c);
        float a0 = xv.x * tv.x + pv.x * (1.f - tv.x);
        float a1 = xv.y * tv.y + pv.y * (1.f - tv.y);
        float a2 = xv.z * tv.z + pv.z * (1.f - tv.z);
        float a3 = xv.w * tv.w + pv.w * (1.f - tv.w);
        const size_t o = (size_t)mix * Mm * Cc + (size_t)m * Cc + c;
        if (mix < 3) {
            __nv_bfloat16 h[4], l[4];
            split2(a0, h[0], l[0]); split2(a1, h[1], l[1]);
            split2(a2, h[2], l[2]); split2(a3, h[3], l[3]);
            *(uint2*)(g_AH + o) = *(const uint2*)h;
            *(uint2*)(g_AL + o) = *(const uint2*)l;
        } else {
            __half h[4];
            h[0] = __float2half(a0); h[1] = __float2half(a1);
            h[2] = __float2half(a2); h[3] = __float2half(a3);
            *(uint2*)(g_AH + o) = *(const uint2*)h;
        }
    }
}

__global__ __launch_bounds__(256) void wconv_kernel(
    const float* __restrict__ w0, const float* __restrict__ w1,
    const float* __restrict__ w2, const float* __restrict__ w3,
    const float* __restrict__ w4)
{
    const size_t idx = (size_t)blockIdx.x * 256 + threadIdx.x;  // over 5*C*C/4
    const size_t per = (size_t)Cc * Cc / 4;
    const int w = (int)(idx / per);
    const size_t e4 = idx - (size_t)w * per;
    const float* ws[5] = {w0, w1, w2, w3, w4};
    float4 v = *(const float4*)(ws[w] + e4 * 4);
    const size_t o = (size_t)w * Cc * Cc + e4 * 4;
    if (w < 3) {
        __nv_bfloat16 h[4], l[4];
        split2(v.x, h[0], l[0]); split2(v.y, h[1], l[1]);
        split2(v.z, h[2], l[2]); split2(v.w, h[3], l[3]);
        *(uint2*)(g_WH + o) = *(const uint2*)h;
        *(uint2*)(g_WL + o) = *(const uint2*)l;
    } else {
        __half h[4];
        h[0] = __float2half(v.x); h[1] = __float2half(v.y);
        h[2] = __float2half(v.z); h[3] = __float2half(v.w);
        *(uint2*)(g_WH + o) = *(const uint2*)h;
    }
}

// ---------------- MODE 0: bf16 3-term GEMM (R,K,V), BK=32 --------------------
#define BM 128
#define BN 128
#define BK 32
#define STG 32768
#define GEMM_SMEM (3*STG)    // 98304

__device__ __forceinline__ void load_chunk0(
    uint32_t sbase, int stage, int kc, int m0, int n0, int tid,
    const __nv_bfloat16* Ah, const __nv_bfloat16* Al,
    const __nv_bfloat16* Bh, const __nv_bfloat16* Bl)
{
    const int k0 = kc * BK;
    const uint32_t s = sbase + stage * STG;
    #pragma unroll
    for (int p = 0; p < 2; p++) {
        const int idx = tid + p * 256;          // 0..511
        const int row = idx >> 2;
        const int ch  = idx & 3;
        const uint32_t off = (uint32_t)(row * 64 + ((ch ^ (row & 3)) << 4));
        const size_t gA = (size_t)(m0 + row) * Cc + k0 + ch * 8;
        const size_t gB = (size_t)(n0 + row) * Cc + k0 + ch * 8;
        CP16(s + off,          (const char*)(Ah + gA));
        CP16(s + 8192  + off,  (const char*)(Al + gA));
        CP16(s + 16384 + off,  (const char*)(Bh + gB));
        CP16(s + 24576 + off,  (const char*)(Bl + gB));
    }
    CP_COMMIT();
}

__device__ __forceinline__ void bgemm0_body(
    const __nv_bfloat16* __restrict__ Ah, const __nv_bfloat16* __restrict__ Al,
    const __nv_bfloat16* __restrict__ Bh, const __nv_bfloat16* __restrict__ Bl,
    float* __restrict__ out, char* smem)
{
    const uint32_t sbase = smem_u32(smem);
    const int tid = threadIdx.x;
    const int wid = tid >> 5;
    const int lane = tid & 31;
    const int m0 = blockIdx.y * BM;
    const int n0 = blockIdx.x * BN;
    const int wm = (wid & 1) * 64;
    const int wn = (wid >> 1) * 32;

    float acc[4][4][4];
    #pragma unroll
    for (int i = 0; i < 4; i++)
        #pragma unroll
        for (int j = 0; j < 4; j++)
            #pragma unroll
            for (int q = 0; q < 4; q++) acc[i][j][q] = 0.f;

    load_chunk0(sbase, 0, 0, m0, n0, tid, Ah, Al, Bh, Bl);
    load_chunk0(sbase, 1, 1, m0, n0, tid, Ah, Al, Bh, Bl);

    const int NCH = Cc / BK;   // 64
    const int tj = lane >> 3;
    const int tr = lane & 7;

    for (int i = 0; i < NCH; i++) {
        if (i < NCH - 2) asm volatile("cp.async.wait_group 1;" ::: "memory");
        else             asm volatile("cp.async.wait_group 0;" ::: "memory");
        __syncthreads();
        if (i + 2 < NCH)
            load_chunk0(sbase, (i + 2) % 3, i + 2, m0, n0, tid, Ah, Al, Bh, Bl);

        const uint32_t s = sbase + (i % 3) * STG;
        #pragma unroll
        for (int ks = 0; ks < 2; ks++) {
            uint32_t aH[4][4], aL[4][4];
            #pragma unroll
            for (int mi = 0; mi < 4; mi++) {
                const int row = wm + mi * 16 + ((tj & 1) << 3) + tr;
                const int ch = 2 * ks + (tj >> 1);
                const uint32_t off = (uint32_t)(row * 64 + ((ch ^ (row & 3)) << 4));
                ldsm4(aH[mi], s + off);
                ldsm4(aL[mi], s + 8192 + off);
            }
            uint32_t bH[4][2], bL[4][2];
            #pragma unroll
            for (int np = 0; np < 2; np++) {
                const int row = wn + np * 16 + ((tj >> 1) << 3) + tr;
                const int ch = 2 * ks + (tj & 1);
                const uint32_t off = (uint32_t)(row * 64 + ((ch ^ (row & 3)) << 4));
                uint32_t rH[4], rL[4];
                ldsm4(rH, s + 16384 + off);
                ldsm4(rL, s + 24576 + off);
                bH[np*2][0]   = rH[0]; bH[np*2][1]   = rH[1];
                bH[np*2+1][0] = rH[2]; bH[np*2+1][1] = rH[3];
                bL[np*2][0]   = rL[0]; bL[np*2][1]   = rL[1];
                bL[np*2+1][0] = rL[2]; bL[np*2+1][1] = rL[3];
            }
            #pragma unroll
            for (int mi = 0; mi < 4; mi++)
                #pragma unroll
                for (int ni = 0; ni < 4; ni++) {
                    mma_bf16(acc[mi][ni], aH[mi], bH[ni]);
                    mma_bf16(acc[mi][ni], aH[mi], bL[ni]);
                    mma_bf16(acc[mi][ni], aL[mi], bH[ni]);
                }
        }
    }

    const int r4 = lane >> 2;
    const int c2 = (lane & 3) * 2;
    #pragma unroll
    for (int mi = 0; mi < 4; mi++) {
        #pragma unroll
        for (int ni = 0; ni < 4; ni++) {
            const int mrow = m0 + wm + mi * 16 + r4;
            const int ncol = n0 + wn + ni * 8 + c2;
            float* p0 = out + (size_t)mrow * Cc + ncol;
            float* p1 = out + (size_t)(mrow + 8) * Cc + ncol;
            p0[0] = acc[mi][ni][0]; p0[1] = acc[mi][ni][1];
            p1[0] = acc[mi][ni][2]; p1[1] = acc[mi][ni][3];
        }
    }
}

__global__ __launch_bounds__(256, 2) void bgemm3_kernel(
    const __nv_bfloat16* __restrict__ AH, const __nv_bfloat16* __restrict__ AL,
    const __nv_bfloat16* __restrict__ WH, const __nv_bfloat16* __restrict__ WL,
    float* o0, float* o1, float* o2)
{
    extern __shared__ char smem[];
    const int z = blockIdx.z;
    const size_t MC = (size_t)Mm * Cc;
    const size_t CC = (size_t)Cc * Cc;
    float* out = (z == 0) ? o0 : (z == 1) ? o1 : o2;
    bgemm0_body(AH + (size_t)z * MC, AL + (size_t)z * MC,
                WH + (size_t)z * CC, WL + (size_t)z * CC, out, smem);
}

// ---------------- MODE 2: fp16 single x single GEMM (G,O), BK=64 ------------
#define BK2 64
#define STG2 32768           // A 16KB + B 16KB
#define GEMM2_SMEM (3*STG2)  // 98304

__device__ __forceinline__ void load_chunk2(
    uint32_t sbase, int stage, int kc, int m0, int n0, int tid,
    const __nv_bfloat16* Ah, const __nv_bfloat16* Bh)
{
    const int k0 = kc * BK2;
    const uint32_t s = sbase + stage * STG2;
    #pragma unroll
    for (int p = 0; p < 4; p++) {
        const int idx = tid + p * 256;          // 0..1023
        const int row = idx >> 3;               // 0..127
        const int ch  = idx & 7;
        const uint32_t off = (uint32_t)(row * 128 + ((ch ^ (row & 7)) << 4));
        const size_t gA = (size_t)(m0 + row) * Cc + k0 + ch * 8;
        const size_t gB = (size_t)(n0 + row) * Cc + k0 + ch * 8;
        CP16(s + off,         (const char*)(Ah + gA));
        CP16(s + 16384 + off, (const char*)(Bh + gB));
    }
    CP_COMMIT();
}

__global__ __launch_bounds__(256, 2) void bgemm2_kernel(
    const __nv_bfloat16* __restrict__ Ah, const __nv_bfloat16* __restrict__ Bh,
    float* __restrict__ out, int do_silu)
{
    extern __shared__ char smem[];
    const uint32_t sbase = smem_u32(smem);
    const int tid = threadIdx.x;
    const int wid = tid >> 5;
    const int lane = tid & 31;
    const int m0 = blockIdx.y * BM;
    const int n0 = blockIdx.x * BN;
    const int wm = (wid & 1) * 64;
    const int wn = (wid >> 1) * 32;

    float acc[4][4][4];
    #pragma unroll
    for (int i = 0; i < 4; i++)
        #pragma unroll
        for (int j = 0; j < 4; j++)
            #pragma unroll
            for (int q = 0; q < 4; q++) acc[i][j][q] = 0.f;

    load_chunk2(sbase, 0, 0, m0, n0, tid, Ah, Bh);
    load_chunk2(sbase, 1, 1, m0, n0, tid, Ah, Bh);

    const int NCH = Cc / BK2;   // 32
    const int tj = lane >> 3;
    const int tr = lane & 7;

    for (int i = 0; i < NCH; i++) {
        if (i < NCH - 2) asm volatile("cp.async.wait_group 1;" ::: "memory");
        else             asm volatile("cp.async.wait_group 0;" ::: "memory");
        __syncthreads();
        if (i + 2 < NCH)
            load_chunk2(sbase, (i + 2) % 3, i + 2, m0, n0, tid, Ah, Bh);

        const uint32_t s = sbase + (i % 3) * STG2;
        #pragma unroll
        for (int ks = 0; ks < 4; ks++) {
            uint32_t aH[4][4];
            #pragma unroll
            for (int mi = 0; mi < 4; mi++) {
                const int row = wm + mi * 16 + ((tj & 1) << 3) + tr;
                const int ch = 2 * ks + (tj >> 1);
                const uint32_t off = (uint32_t)(row * 128 + ((ch ^ (row & 7)) << 4));
                ldsm4(aH[mi], s + off);
            }
            uint32_t bH[4][2];
            #pragma unroll
            for (int np = 0; np < 2; np++) {
                const int row = wn + np * 16 + ((tj >> 1) << 3) + tr;
                const int ch = 2 * ks + (tj & 1);
                const uint32_t off = (uint32_t)(row * 128 + ((ch ^ (row & 7)) << 4));
                uint32_t rH[4];
                ldsm4(rH, s + 16384 + off);
                bH[np*2][0]   = rH[0]; bH[np*2][1]   = rH[1];
                bH[np*2+1][0] = rH[2]; bH[np*2+1][1] = rH[3];
            }
            #pragma unroll
            for (int mi = 0; mi < 4; mi++)
                #pragma unroll
                for (int ni = 0; ni < 4; ni++)
                    mma_fp16(acc[mi][ni], aH[mi], bH[ni]);
        }
    }

    const int r4 = lane >> 2;
    const int c2 = (lane & 3) * 2;
    #pragma unroll
    for (int mi = 0; mi < 4; mi++) {
        #pragma unroll
        for (int ni = 0; ni < 4; ni++) {
            float v[4];
            #pragma unroll
            for (int q = 0; q < 4; q++) {
                float f = acc[mi][ni][q];
                if (do_silu) f = f / (1.f + expf(-f));
                v[q] = f;
            }
            const int mrow = m0 + wm + mi * 16 + r4;
            const int ncol = n0 + wn + ni * 8 + c2;
            float* p0 = out + (size_t)mrow * Cc + ncol;
            float* p1 = out + (size_t)(mrow + 8) * Cc + ncol;
            p0[0] = v[0]; p0[1] = v[1];
            p1[0] = v[2]; p1[1] = v[3];
        }
    }
}

// ---------------- base -------------------------------------------------------
__global__ __launch_bounds__(256) void base_kernel(
    const float* __restrict__ wkvstate, const float* __restrict__ tdecay,
    const float* __restrict__ faaaa, const float* __restrict__ R,
    const float* __restrict__ Kbuf, const float* __restrict__ V,
    float* __restrict__ wkv)
{
    __shared__ __align__(16) float S0s[64 * 68];
    __shared__ __align__(16) float rws[64 * 68];
    __shared__ float dotu4[64][4];
    __shared__ float dotu[64];
    __shared__ float l2w[64], us[64];

    const int bh = blockIdx.x;
    const int b = bh >> 5, h = bh & 31;
    const int t0 = blockIdx.y << 6;
    const int tid = threadIdx.x;

    if (tid < 64) {
        float e = expf(tdecay[h * 64 + tid]);
        l2w[tid] = -e * 1.4426950408889634f;
        us[tid] = faaaa[h * 64 + tid];
    }
    for (int i = tid; i < 4096; i += 256)
        S0s[(i >> 6) * 68 + (i & 63)] = wkvstate[h * 4096 + i];
    __syncthreads();

    {
        const int row = tid >> 2;
        const int kb = (tid & 3) << 4;
        const int t = t0 + row;
        const float* rp = R    + (size_t)(b * Tt + t) * Cc + h * 64;
        const float* kp = Kbuf + (size_t)(b * Tt + t) * Cc + h * 64;
        float part = 0.f;
        const float tf = (float)t;
        #pragma unroll
        for (int kk = 0; kk < 16; kk++) {
            const int k = kb + kk;
            float rv = rp[k];
            rws[row * 68 + k] = rv * exp2f(tf * l2w[k]);
            part += rv * kp[k] * us[k];
        }
        dotu4[row][tid & 3] = part;
    }
    __syncthreads();
    if (tid < 64)
        dotu[tid] = dotu4[tid][0] + dotu4[tid][1] + dotu4[tid][2] + dotu4[tid][3];
    __syncthreads();

    const int tx = tid & 15, ty = tid >> 4;
    float acc[4][4];
    #pragma unroll
    for (int i = 0; i < 4; i++)
        #pragma unroll
        for (int j = 0; j < 4; j++) acc[i][j] = 0.f;

    for (int k0 = 0; k0 < 64; k0 += 4) {
        float4 av[4], bv[4];
        #pragma unroll
        for (int i = 0; i < 4; i++)
            av[i] = *(const float4*)&rws[(ty * 4 + i) * 68 + k0];
        #pragma unroll
        for (int kk = 0; kk < 4; kk++)
            bv[kk] = *(const float4*)&S0s[(k0 + kk) * 68 + tx * 4];
        #pragma unroll
        for (int i = 0; i < 4; i++) {
            acc[i][0] += av[i].x * bv[0].x + av[i].y * bv[1].x
                       + av[i].z * bv[2].x + av[i].w * bv[3].x;
            acc[i][1] += av[i].x * bv[0].y + av[i].y * bv[1].y
                       + av[i].z * bv[2].y + av[i].w * bv[3].y;
            acc[i][2] += av[i].x * bv[0].z + av[i].y * bv[1].z
                       + av[i].z * bv[2].z + av[i].w * bv[3].z;
            acc[i][3] += av[i].x * bv[0].w + av[i].y * bv[1].w
                       + av[i].z * bv[2].w + av[i].w * bv[3].w;
        }
    }

    #pragma unroll
    for (int i = 0; i < 4; i++) {
        const int p = ty * 4 + i;
        const int t = t0 + p;
        const float* vp = V + (size_t)(b * Tt + t) * Cc + h * 64;
        const float du = dotu[p];
        float* wp = wkv + ((size_t)(b * Hh + h) * Tt + t) * 64;
        #pragma unroll
        for (int j = 0; j < 4; j++) {
            const int jn = tx * 4 + j;
            wp[jn] = acc[i][j] + du * vp[jn];
        }
    }
}

// ---------------- chunked intra scan: 256 thr, 4x4 tiles, padded rows -------
#define SPAD 68
__global__ __launch_bounds__(256) void scan_kernel(
    const float* __restrict__ tdecay,
    const float* __restrict__ R, const float* __restrict__ Kbuf,
    const float* __restrict__ V, float* __restrict__ intra)
{
    extern __shared__ float sm[];
    float* Ssm  = sm;                    // 64*68
    float* rcs  = Ssm  + 64*SPAD;
    float* kcs  = rcs  + 64*SPAD;
    float* vcs  = kcs  + 64*SPAD;
    float* atts = vcs  + 64*SPAD;
    float* l2w  = atts + 64*SPAD;        // 64

    const int b = blockIdx.x >> 5, h = blockIdx.x & 31;
    const int tid = threadIdx.x;

    if (tid < 64)
        l2w[tid] = -expf(tdecay[h * 64 + tid]) * 1.4426950408889634f;
    for (int i = tid; i < 64*SPAD; i += 256) Ssm[i] = 0.f;
    __syncthreads();

    const int tx = tid & 15, ty = tid >> 4;   // 4-col group, 4-row group
    const int lrow = tid >> 2;                // 0..63
    const int kb16 = (tid & 3) << 4;          // 16 elems per thread

    for (int ci = 0; ci < 32; ci++) {
        const int q0 = ci << 6;
        {
            const int tq = q0 + lrow;
            const int tr = tq + 1;
            const bool kvv = (tq < Tt - 1);
            const bool rvv = (tr < Tt);
            const float* rp = R    + (size_t)(b * Tt + tr) * Cc + h * 64;
            const float* kp = Kbuf + (size_t)(b * Tt + tq) * Cc + h * 64;
            const float* vp = V    + (size_t)(b * Tt + tq) * Cc + h * 64;
            const float wexp = (float)(Tt - 1 - tq);
            #pragma unroll
            for (int v4 = 0; v4 < 4; v4++) {
                const int k = kb16 + v4 * 4;
                float4 rv = rvv ? *(const float4*)(rp + k)
                                : make_float4(0.f, 0.f, 0.f, 0.f);
                float4 kv = make_float4(0.f, 0.f, 0.f, 0.f);
                float4 vv = make_float4(0.f, 0.f, 0.f, 0.f);
                if (kvv) {
                    float4 kraw = *(const float4*)(kp + k);
                    vv = *(const float4*)(vp + k);
                    kv.x = kraw.x * exp2f(wexp * l2w[k]);
                    kv.y = kraw.y * exp2f(wexp * l2w[k + 1]);
                    kv.z = kraw.z * exp2f(wexp * l2w[k + 2]);
                    kv.w = kraw.w * exp2f(wexp * l2w[k + 3]);
                }
                *(float4*)&rcs[lrow * SPAD + k] = rv;
                *(float4*)&kcs[lrow * SPAD + k] = kv;
                *(float4*)&vcs[lrow * SPAD + k] = vv;
            }
        }
        __syncthreads();

        // merged loop 1: att = r·k^T, dS = k^T·v
        float att[4][4], dS[4][4];
        #pragma unroll
        for (int i = 0; i < 4; i++)
            #pragma unroll
            for (int j = 0; j < 4; j++) { att[i][j] = 0.f; dS[i][j] = 0.f; }

        for (int q = 0; q < 64; q++) {
            float ra[4], kb_[4];
            #pragma unroll
            for (int i = 0; i < 4; i++) ra[i] = rcs[(ty * 4 + i) * SPAD + q];
            #pragma unroll
            for (int j = 0; j < 4; j++) kb_[j] = kcs[(tx * 4 + j) * SPAD + q];
            float4 ka = *(const float4*)&kcs[q * SPAD + ty * 4];
            float4 vb = *(const float4*)&vcs[q * SPAD + tx * 4];
            const float kav[4] = {ka.x, ka.y, ka.z, ka.w};
            const float vbv[4] = {vb.x, vb.y, vb.z, vb.w};
            #pragma unroll
            for (int i = 0; i < 4; i++)
                #pragma unroll
                for (int j = 0; j < 4; j++) {
                    att[i][j] += ra[i] * kb_[j];
                    dS[i][j]  += kav[i] * vbv[j];
                }
        }
        #pragma unroll
        for (int i = 0; i < 4; i++) {
            float4 w;
            w.x = ((tx * 4 + 0) <= (ty * 4 + i)) ? att[i][0] : 0.f;
            w.y = ((tx * 4 + 1) <= (ty * 4 + i)) ? att[i][1] : 0.f;
            w.z = ((tx * 4 + 2) <= (ty * 4 + i)) ? att[i][2] : 0.f;
            w.w = ((tx * 4 + 3) <= (ty * 4 + i)) ? att[i][3] : 0.f;
            *(float4*)&atts[(ty * 4 + i) * SPAD + tx * 4] = w;
        }
        __syncthreads();

        // merged loop 2: o = atts·v + r·S
        float o[4][4];
        #pragma unroll
        for (int i = 0; i < 4; i++)
            #pragma unroll
            for (int j = 0; j < 4; j++) o[i][j] = 0.f;

        for (int q = 0; q < 64; q++) {
            float aa[4], ra[4];
            #pragma unroll
            for (int i = 0; i < 4; i++) aa[i] = atts[(ty * 4 + i) * SPAD + q];
            #pragma unroll
            for (int i = 0; i < 4; i++) ra[i] = rcs[(ty * 4 + i) * SPAD + q];
            float4 vb = *(const float4*)&vcs[q * SPAD + tx * 4];
            float4 sb = *(const float4*)&Ssm[q * SPAD + tx * 4];
            const float vbv[4] = {vb.x, vb.y, vb.z, vb.w};
            const float sbv[4] = {sb.x, sb.y, sb.z, sb.w};
            #pragma unroll
            for (int i = 0; i < 4; i++)
                #pragma unroll
                for (int j = 0; j < 4; j++)
                    o[i][j] += aa[i] * vbv[j] + ra[i] * sbv[j];
        }

        #pragma unroll
        for (int i = 0; i < 4; i++) {
            const int gt = q0 + ty * 4 + i + 1;
            if (gt < Tt) {
                float* wp = intra + ((size_t)(b * Hh + h) * Tt + gt) * 64 + tx * 4;
                *(float4*)wp = make_float4(o[i][0], o[i][1], o[i][2], o[i][3]);
            }
        }
        __syncthreads();

        #pragma unroll
        for (int i = 0; i < 4; i++) {
            float* sp = &Ssm[(ty * 4 + i) * SPAD + tx * 4];
            float4 sv = *(float4*)sp;
            sv.x += dS[i][0]; sv.y += dS[i][1];
            sv.z += dS[i][2]; sv.w += dS[i][3];
            *(float4*)sp = sv;
        }
    }
}

// ---------------- groupnorm: (wkv+intra) -> bf16 round -> gn -> gate --------
__global__ __launch_bounds__(256) void gn_kernel(
    const float* __restrict__ lnw, const float* __restrict__ lnb,
    const float* __restrict__ wkv, const float* __restrict__ intra,
    const float* __restrict__ gbuf)
{
    const int g = blockIdx.x * 8 + (threadIdx.x >> 5);
    const int lane = threadIdx.x & 31;
    const int b = g >> 16;
    const int rem = g & 65535;
    const int t = rem >> 5;
    const int h = rem & 31;

    const size_t wi = ((size_t)(b * Hh + h) * Tt + t) * 64;
    const float* wp = wkv + wi;
    const float* ip = intra + wi;
    float s0 = wp[lane];
    float s1 = wp[lane + 32];
    if (t > 0) { s0 += ip[lane]; s1 += ip[lane + 32]; }
    float v0 = __bfloat162float(__float2bfloat16(s0));
    float v1 = __bfloat162float(__float2bfloat16(s1));
    float s = v0 + v1;
    float ss = v0 * v0 + v1 * v1;
    #pragma unroll
    for (int off = 16; off; off >>= 1) {
        s  += __shfl_xor_sync(0xffffffffu, s,  off);
        ss += __shfl_xor_sync(0xffffffffu, ss, off);
    }
    const float mu  = s * (1.f / 64.f);
    const float var = ss * (1.f / 64.f) - mu * mu;
    const float inv = rsqrtf(var + EPSV);

    const int c0 = h * 64 + lane;
    const size_t gi = (size_t)(b * Tt + t) * Cc + c0;
    const float y0 = ((v0 - mu) * inv * lnw[c0]      + lnb[c0])      * gbuf[gi];
    const float y1 = ((v1 - mu) * inv * lnw[c0 + 32] + lnb[c0 + 32]) * gbuf[gi + 32];
    __half* yh = reinterpret_cast<__half*>(g_YH);
    yh[gi]      = __float2half(y0);
    yh[gi + 32] = __float2half(y1);
}

// ---------------- launch ----------------------------------------------------
extern "C" void kernel_launch(void* const* d_in, const int* in_sizes, int n_in,
                              void* d_out, int out_size)
{
    const float* x        = (const float*)d_in[0];
    const float* state    = (const float*)d_in[1];
    const float* wkvstate = (const float*)d_in[2];
    const float* tmk      = (const float*)d_in[3];
    const float* tmv      = (const float*)d_in[4];
    const float* tmr      = (const float*)d_in[5];
    const float* tmg      = (const float*)d_in[6];
    const float* tdecay   = (const float*)d_in[7];
    const float* faaaa    = (const float*)d_in[8];
    const float* w_r      = (const float*)d_in[9];
    const float* w_k      = (const float*)d_in[10];
    const float* w_v      = (const float*)d_in[11];
    const float* w_g      = (const float*)d_in[12];
    const float* w_o      = (const float*)d_in[13];
    const float* ln_w     = (const float*)d_in[14];
    const float* ln_b     = (const float*)d_in[15];
    float* out = (float*)d_out;

    float *pR, *pK, *pV, *pG, *pW, *pI;
    cudaGetSymbolAddress((void**)&pR, g_R);
    cudaGetSymbolAddress((void**)&pK, g_Kb);
    cudaGetSymbolAddress((void**)&pV, g_V);
    cudaGetSymbolAddress((void**)&pG, g_G);
    cudaGetSymbolAddress((void**)&pW, g_WKV);
    cudaGetSymbolAddress((void**)&pI, g_IN);
    __nv_bfloat16 *pAH, *pAL, *pWH, *pWL, *pYH;
    cudaGetSymbolAddress((void**)&pAH, g_AH);
    cudaGetSymbolAddress((void**)&pAL, g_AL);
    cudaGetSymbolAddress((void**)&pWH, g_WH);
    cudaGetSymbolAddress((void**)&pWL, g_WL);
    cudaGetSymbolAddress((void**)&pYH, g_YH);

    static cudaStream_t s1 = nullptr, s2 = nullptr;
    static cudaEvent_t evFork = nullptr, evW = nullptr, evMix = nullptr,
                       evRKV = nullptr, evG = nullptr, evBase = nullptr;
    if (s1 == nullptr) {
        cudaStreamCreateWithFlags(&s1, cudaStreamNonBlocking);
        cudaStreamCreateWithFlags(&s2, cudaStreamNonBlocking);
        cudaEventCreateWithFlags(&evFork, cudaEventDisableTiming);
        cudaEventCreateWithFlags(&evW,    cudaEventDisableTiming);
        cudaEventCreateWithFlags(&evMix,  cudaEventDisableTiming);
        cudaEventCreateWithFlags(&evRKV,  cudaEventDisableTiming);
        cudaEventCreateWithFlags(&evG,    cudaEventDisableTiming);
        cudaEventCreateWithFlags(&evBase, cudaEventDisableTiming);
    }

    const int scan_smem = (5 * 64 * SPAD + 64) * 4;   // 87296
    cudaFuncSetAttribute(scan_kernel,
                         cudaFuncAttributeMaxDynamicSharedMemorySize, scan_smem);
    cudaFuncSetAttribute(bgemm3_kernel,
                         cudaFuncAttributeMaxDynamicSharedMemorySize, GEMM_SMEM);
    cudaFuncSetAttribute(bgemm2_kernel,
                         cudaFuncAttributeMaxDynamicSharedMemorySize, GEMM2_SMEM);

    const size_t MC = (size_t)Mm * Cc;
    const size_t CC = (size_t)Cc * Cc;

    dim3 gg(Cc / BN, Mm / BM);        // (16, 64)
    dim3 gg3(Cc / BN, Mm / BM, 3);    // (16, 64, 3)

    // fork s1 from capture-origin stream
    cudaEventRecord(evFork, 0);
    cudaStreamWaitEvent(s1, evFork, 0);

    // s1: wconv (independent of mixconv)
    wconv_kernel<<<(int)(5 * CC / 4 / 256), 256, 0, s1>>>(w_r, w_k, w_v, w_g, w_o);
    cudaEventRecord(evW, s1);

    // default: mixconv
    mixconv_kernel<<<(int)(MC / 4 / 256), 256>>>(x, state, tmr, tmk, tmv, tmg);
    cudaEventRecord(evMix, 0);

    // s1: G projection (fp16 1-term, BK=64) after mixconv done
    cudaStreamWaitEvent(s1, evMix, 0);
    bgemm2_kernel<<<gg, 256, GEMM2_SMEM, s1>>>(pAH + 3*MC, pWH + 3*CC, pG, 1);
    cudaEventRecord(evG, s1);

    // default: RKV GEMM (bf16 3-term) after wconv done
    cudaStreamWaitEvent(0, evW, 0);
    bgemm3_kernel<<<gg3, 256, GEMM_SMEM>>>(pAH, pAL, pWH, pWL, pR, pK, pV);
    cudaEventRecord(evRKV, 0);

    // s2: base overlapped with scan
    cudaStreamWaitEvent(s2, evRKV, 0);
    base_kernel<<<dim3(Bb * Hh, Tt / 64), 256, 0, s2>>>(wkvstate, tdecay, faaaa,
                                                        pR, pK, pV, pW);
    cudaEventRecord(evBase, s2);

    // default: scan
    scan_kernel<<<Bb * Hh, 256, scan_smem>>>(tdecay, pR, pK, pV, pI);

    // join for gn
    cudaStreamWaitEvent(0, evG, 0);
    cudaStreamWaitEvent(0, evBase, 0);
    gn_kernel<<<(Bb * Tt * Hh) / 8, 256>>>(ln_w, ln_b, pW, pI, pG);

    // final O projection (fp16 1-term, BK=64)
    bgemm2_kernel<<<gg, 256, GEMM2_SMEM>>>(pYH, pWH + 4*CC, out, 0);
}

// round 16
// speedup vs baseline: 1.0874x; 1.0874x over previous
#include <cuda_runtime.h>
#include <cuda_bf16.h>
#include <cuda_fp16.h>
#include <cstdint>
#include <cstddef>

// Problem constants
#define Bb 4
#define Tt 2048
#define Cc 2048
#define Hh 32
#define Kk 64
#define Mm (Bb*Tt)          // 8192
#define EPSV 0.00064f

// ---------------- scratch (device globals; no allocation allowed) ----------
__device__ __align__(256) __nv_bfloat16 g_AH[(size_t)4*Mm*Cc];
__device__ __align__(256) __nv_bfloat16 g_AL[(size_t)3*Mm*Cc];
__device__ __align__(256) __nv_bfloat16 g_WH[(size_t)5*Cc*Cc];
__device__ __align__(256) __nv_bfloat16 g_WL[(size_t)3*Cc*Cc];
__device__ __align__(256) __nv_bfloat16 g_YH[(size_t)Mm*Cc];   // fp16 payload
__device__ float g_R[(size_t)Mm*Cc];
__device__ float g_Kb[(size_t)Mm*Cc];
__device__ float g_V[(size_t)Mm*Cc];
__device__ float g_G[(size_t)Mm*Cc];
__device__ float g_WKV[(size_t)Mm*Cc];   // base term
__device__ float g_IN[(size_t)Mm*Cc];    // intra term (t>=1 valid)

// ---------------- helpers ----------------------------------------------------
__device__ __forceinline__ uint32_t smem_u32(const void* p) {
    uint32_t a;
    asm("{ .reg .u64 t; cvta.to.shared.u64 t, %1; cvt.u32.u64 %0, t; }"
        : "=r"(a) : "l"(p));
    return a;
}
#define CP16(dst, src) \
    asm volatile("cp.async.cg.shared.global [%0], [%1], 16;" :: "r"(dst), "l"(src))
#define CP_COMMIT() asm volatile("cp.async.commit_group;" ::: "memory")

__device__ __forceinline__ void ldsm4(uint32_t* r, uint32_t addr) {
    asm volatile("ldmatrix.sync.aligned.m8n8.x4.shared.b16 {%0,%1,%2,%3}, [%4];"
                 : "=r"(r[0]), "=r"(r[1]), "=r"(r[2]), "=r"(r[3]) : "r"(addr));
}
__device__ __forceinline__ void mma_bf16(float* c, const uint32_t* a,
                                         const uint32_t* b) {
    asm volatile(
        "mma.sync.aligned.m16n8k16.row.col.f32.bf16.bf16.f32 "
        "{%0,%1,%2,%3}, {%4,%5,%6,%7}, {%8,%9}, {%0,%1,%2,%3};"
        : "+f"(c[0]), "+f"(c[1]), "+f"(c[2]), "+f"(c[3])
        : "r"(a[0]), "r"(a[1]), "r"(a[2]), "r"(a[3]), "r"(b[0]), "r"(b[1]));
}
__device__ __forceinline__ void mma_fp16(float* c, const uint32_t* a,
                                         const uint32_t* b) {
    asm volatile(
        "mma.sync.aligned.m16n8k16.row.col.f32.f16.f16.f32 "
        "{%0,%1,%2,%3}, {%4,%5,%6,%7}, {%8,%9}, {%0,%1,%2,%3};"
        : "+f"(c[0]), "+f"(c[1]), "+f"(c[2]), "+f"(c[3])
        : "r"(a[0]), "r"(a[1]), "r"(a[2]), "r"(a[3]), "r"(b[0]), "r"(b[1]));
}
__device__ __forceinline__ void split2(float a, __nv_bfloat16& h, __nv_bfloat16& l) {
    h = __float2bfloat16(a);
    l = __float2bfloat16(a - __bfloat162float(h));
}

// ---------------- conversion kernels ----------------------------------------
__global__ __launch_bounds__(256) void mixconv_kernel(
    const float* __restrict__ x, const float* __restrict__ state,
    const float* __restrict__ tmr, const float* __restrict__ tmk,
    const float* __restrict__ tmv, const float* __restrict__ tmg)
{
    const size_t idx = (size_t)blockIdx.x * 256 + threadIdx.x;   // over M*C/4
    const int m = (int)(idx >> 9);
    const int c = ((int)idx & 511) << 2;
    const int t = m & (Tt - 1);

    float4 xv = *(const float4*)(x + (size_t)m * Cc + c);
    float4 pv = (t == 0) ? *(const float4*)(state + c)
                         : *(const float4*)(x + (size_t)(m - 1) * Cc + c);
    const float* tms[4] = {tmr, tmk, tmv, tmg};
    #pragma unroll
    for (int mix = 0; mix < 4; mix++) {
        float4 tv = *(const float4*)(tms[mix] + c);
        float a0 = xv.x * tv.x + pv.x * (1.f - tv.x);
        float a1 = xv.y * tv.y + pv.y * (1.f - tv.y);
        float a2 = xv.z * tv.z + pv.z * (1.f - tv.z);
        float a3 = xv.w * tv.w + pv.w * (1.f - tv.w);
        const size_t o = (size_t)mix * Mm * Cc + (size_t)m * Cc + c;
        if (mix < 3) {
            __nv_bfloat16 h[4], l[4];
            split2(a0, h[0], l[0]); split2(a1, h[1], l[1]);
            split2(a2, h[2], l[2]); split2(a3, h[3], l[3]);
            *(uint2*)(g_AH + o) = *(const uint2*)h;
            *(uint2*)(g_AL + o) = *(const uint2*)l;
        } else {
            __half h[4];
            h[0] = __float2half(a0); h[1] = __float2half(a1);
            h[2] = __float2half(a2); h[3] = __float2half(a3);
            *(uint2*)(g_AH + o) = *(const uint2*)h;
        }
    }
}

__global__ __launch_bounds__(256) void wconv_kernel(
    const float* __restrict__ w0, const float* __restrict__ w1,
    const float* __restrict__ w2, const float* __restrict__ w3,
    const float* __restrict__ w4)
{
    const size_t idx = (size_t)blockIdx.x * 256 + threadIdx.x;  // over 5*C*C/4
    const size_t per = (size_t)Cc * Cc / 4;
    const int w = (int)(idx / per);
    const size_t e4 = idx - (size_t)w * per;
    const float* ws[5] = {w0, w1, w2, w3, w4};
    float4 v = *(const float4*)(ws[w] + e4 * 4);
    const size_t o = (size_t)w * Cc * Cc + e4 * 4;
    if (w < 3) {
        __nv_bfloat16 h[4], l[4];
        split2(v.x, h[0], l[0]); split2(v.y, h[1], l[1]);
        split2(v.z, h[2], l[2]); split2(v.w, h[3], l[3]);
        *(uint2*)(g_WH + o) = *(const uint2*)h;
        *(uint2*)(g_WL + o) = *(const uint2*)l;
    } else {
        __half h[4];
        h[0] = __float2half(v.x); h[1] = __float2half(v.y);
        h[2] = __float2half(v.z); h[3] = __float2half(v.w);
        *(uint2*)(g_WH + o) = *(const uint2*)h;
    }
}

// ---------------- MODE 0: bf16 3-term GEMM (R,K,V), BK=32 --------------------
#define BM 128
#define BN 128
#define BK 32
#define STG 32768
#define GEMM_SMEM (3*STG)    // 98304

__device__ __forceinline__ void load_chunk0(
    uint32_t sbase, int stage, int kc, int m0, int n0, int tid,
    const __nv_bfloat16* Ah, const __nv_bfloat16* Al,
    const __nv_bfloat16* Bh, const __nv_bfloat16* Bl)
{
    const int k0 = kc * BK;
    const uint32_t s = sbase + stage * STG;
    #pragma unroll
    for (int p = 0; p < 2; p++) {
        const int idx = tid + p * 256;          // 0..511
        const int row = idx >> 2;
        const int ch  = idx & 3;
        const uint32_t off = (uint32_t)(row * 64 + ((ch ^ (row & 3)) << 4));
        const size_t gA = (size_t)(m0 + row) * Cc + k0 + ch * 8;
        const size_t gB = (size_t)(n0 + row) * Cc + k0 + ch * 8;
        CP16(s + off,          (const char*)(Ah + gA));
        CP16(s + 8192  + off,  (const char*)(Al + gA));
        CP16(s + 16384 + off,  (const char*)(Bh + gB));
        CP16(s + 24576 + off,  (const char*)(Bl + gB));
    }
    CP_COMMIT();
}

__device__ __forceinline__ void bgemm0_body(
    const __nv_bfloat16* __restrict__ Ah, const __nv_bfloat16* __restrict__ Al,
    const __nv_bfloat16* __restrict__ Bh, const __nv_bfloat16* __restrict__ Bl,
    float* __restrict__ out, char* smem)
{
    const uint32_t sbase = smem_u32(smem);
    const int tid = threadIdx.x;
    const int wid = tid >> 5;
    const int lane = tid & 31;
    const int m0 = blockIdx.y * BM;
    const int n0 = blockIdx.x * BN;
    const int wm = (wid & 1) * 64;
    const int wn = (wid >> 1) * 32;

    float acc[4][4][4];
    #pragma unroll
    for (int i = 0; i < 4; i++)
        #pragma unroll
        for (int j = 0; j < 4; j++)
            #pragma unroll
            for (int q = 0; q < 4; q++) acc[i][j][q] = 0.f;

    load_chunk0(sbase, 0, 0, m0, n0, tid, Ah, Al, Bh, Bl);
    load_chunk0(sbase, 1, 1, m0, n0, tid, Ah, Al, Bh, Bl);

    const int NCH = Cc / BK;   // 64
    const int tj = lane >> 3;
    const int tr = lane & 7;

    for (int i = 0; i < NCH; i++) {
        if (i < NCH - 2) asm volatile("cp.async.wait_group 1;" ::: "memory");
        else             asm volatile("cp.async.wait_group 0;" ::: "memory");
        __syncthreads();
        if (i + 2 < NCH)
            load_chunk0(sbase, (i + 2) % 3, i + 2, m0, n0, tid, Ah, Al, Bh, Bl);

        const uint32_t s = sbase + (i % 3) * STG;
        #pragma unroll
        for (int ks = 0; ks < 2; ks++) {
            uint32_t aH[4][4], aL[4][4];
            #pragma unroll
            for (int mi = 0; mi < 4; mi++) {
                const int row = wm + mi * 16 + ((tj & 1) << 3) + tr;
                const int ch = 2 * ks + (tj >> 1);
                const uint32_t off = (uint32_t)(row * 64 + ((ch ^ (row & 3)) << 4));
                ldsm4(aH[mi], s + off);
                ldsm4(aL[mi], s + 8192 + off);
            }
            uint32_t bH[4][2], bL[4][2];
            #pragma unroll
            for (int np = 0; np < 2; np++) {
                const int row = wn + np * 16 + ((tj >> 1) << 3) + tr;
                const int ch = 2 * ks + (tj & 1);
                const uint32_t off = (uint32_t)(row * 64 + ((ch ^ (row & 3)) << 4));
                uint32_t rH[4], rL[4];
                ldsm4(rH, s + 16384 + off);
                ldsm4(rL, s + 24576 + off);
                bH[np*2][0]   = rH[0]; bH[np*2][1]   = rH[1];
                bH[np*2+1][0] = rH[2]; bH[np*2+1][1] = rH[3];
                bL[np*2][0]   = rL[0]; bL[np*2][1]   = rL[1];
                bL[np*2+1][0] = rL[2]; bL[np*2+1][1] = rL[3];
            }
            #pragma unroll
            for (int mi = 0; mi < 4; mi++)
                #pragma unroll
                for (int ni = 0; ni < 4; ni++) {
                    mma_bf16(acc[mi][ni], aH[mi], bH[ni]);
                    mma_bf16(acc[mi][ni], aH[mi], bL[ni]);
                    mma_bf16(acc[mi][ni], aL[mi], bH[ni]);
                }
        }
    }

    const int r4 = lane >> 2;
    const int c2 = (lane & 3) * 2;
    #pragma unroll
    for (int mi = 0; mi < 4; mi++) {
        #pragma unroll
        for (int ni = 0; ni < 4; ni++) {
            const int mrow = m0 + wm + mi * 16 + r4;
            const int ncol = n0 + wn + ni * 8 + c2;
            float* p0 = out + (size_t)mrow * Cc + ncol;
            float* p1 = out + (size_t)(mrow + 8) * Cc + ncol;
            p0[0] = acc[mi][ni][0]; p0[1] = acc[mi][ni][1];
            p1[0] = acc[mi][ni][2]; p1[1] = acc[mi][ni][3];
        }
    }
}

__global__ __launch_bounds__(256, 2) void bgemm3_kernel(
    const __nv_bfloat16* __restrict__ AH, const __nv_bfloat16* __restrict__ AL,
    const __nv_bfloat16* __restrict__ WH, const __nv_bfloat16* __restrict__ WL,
    float* o0, float* o1, float* o2)
{
    extern __shared__ char smem[];
    const int z = blockIdx.z;
    const size_t MC = (size_t)Mm * Cc;
    const size_t CC = (size_t)Cc * Cc;
    float* out = (z == 0) ? o0 : (z == 1) ? o1 : o2;
    bgemm0_body(AH + (size_t)z * MC, AL + (size_t)z * MC,
                WH + (size_t)z * CC, WL + (size_t)z * CC, out, smem);
}

// ---------------- MODE 2: fp16 single x single GEMM (G,O), BK=64 ------------
#define BK2 64
#define STG2 32768           // A 16KB + B 16KB
#define GEMM2_SMEM (3*STG2)  // 98304

__device__ __forceinline__ void load_chunk2(
    uint32_t sbase, int stage, int kc, int m0, int n0, int tid,
    const __nv_bfloat16* Ah, const __nv_bfloat16* Bh)
{
    const int k0 = kc * BK2;
    const uint32_t s = sbase + stage * STG2;
    #pragma unroll
    for (int p = 0; p < 4; p++) {
        const int idx = tid + p * 256;          // 0..1023
        const int row = idx >> 3;               // 0..127
        const int ch  = idx & 7;
        const uint32_t off = (uint32_t)(row * 128 + ((ch ^ (row & 7)) << 4));
        const size_t gA = (size_t)(m0 + row) * Cc + k0 + ch * 8;
        const size_t gB = (size_t)(n0 + row) * Cc + k0 + ch * 8;
        CP16(s + off,         (const char*)(Ah + gA));
        CP16(s + 16384 + off, (const char*)(Bh + gB));
    }
    CP_COMMIT();
}

__global__ __launch_bounds__(256, 2) void bgemm2_kernel(
    const __nv_bfloat16* __restrict__ Ah, const __nv_bfloat16* __restrict__ Bh,
    float* __restrict__ out, int do_silu)
{
    extern __shared__ char smem[];
    const uint32_t sbase = smem_u32(smem);
    const int tid = threadIdx.x;
    const int wid = tid >> 5;
    const int lane = tid & 31;
    const int m0 = blockIdx.y * BM;
    const int n0 = blockIdx.x * BN;
    const int wm = (wid & 1) * 64;
    const int wn = (wid >> 1) * 32;

    float acc[4][4][4];
    #pragma unroll
    for (int i = 0; i < 4; i++)
        #pragma unroll
        for (int j = 0; j < 4; j++)
            #pragma unroll
            for (int q = 0; q < 4; q++) acc[i][j][q] = 0.f;

    load_chunk2(sbase, 0, 0, m0, n0, tid, Ah, Bh);
    load_chunk2(sbase, 1, 1, m0, n0, tid, Ah, Bh);

    const int NCH = Cc / BK2;   // 32
    const int tj = lane >> 3;
    const int tr = lane & 7;

    for (int i = 0; i < NCH; i++) {
        if (i < NCH - 2) asm volatile("cp.async.wait_group 1;" ::: "memory");
        else             asm volatile("cp.async.wait_group 0;" ::: "memory");
        __syncthreads();
        if (i + 2 < NCH)
            load_chunk2(sbase, (i + 2) % 3, i + 2, m0, n0, tid, Ah, Bh);

        const uint32_t s = sbase + (i % 3) * STG2;
        #pragma unroll
        for (int ks = 0; ks < 4; ks++) {
            uint32_t aH[4][4];
            #pragma unroll
            for (int mi = 0; mi < 4; mi++) {
                const int row = wm + mi * 16 + ((tj & 1) << 3) + tr;
                const int ch = 2 * ks + (tj >> 1);
                const uint32_t off = (uint32_t)(row * 128 + ((ch ^ (row & 7)) << 4));
                ldsm4(aH[mi], s + off);
            }
            uint32_t bH[4][2];
            #pragma unroll
            for (int np = 0; np < 2; np++) {
                const int row = wn + np * 16 + ((tj >> 1) << 3) + tr;
                const int ch = 2 * ks + (tj & 1);
                const uint32_t off = (uint32_t)(row * 128 + ((ch ^ (row & 7)) << 4));
                uint32_t rH[4];
                ldsm4(rH, s + 16384 + off);
                bH[np*2][0]   = rH[0]; bH[np*2][1]   = rH[1];
                bH[np*2+1][0] = rH[2]; bH[np*2+1][1] = rH[3];
            }
            #pragma unroll
            for (int mi = 0; mi < 4; mi++)
                #pragma unroll
                for (int ni = 0; ni < 4; ni++)
                    mma_fp16(acc[mi][ni], aH[mi], bH[ni]);
        }
    }

    const int r4 = lane >> 2;
    const int c2 = (lane & 3) * 2;
    #pragma unroll
    for (int mi = 0; mi < 4; mi++) {
        #pragma unroll
        for (int ni = 0; ni < 4; ni++) {
            float v[4];
            #pragma unroll
            for (int q = 0; q < 4; q++) {
                float f = acc[mi][ni][q];
                if (do_silu) f = f / (1.f + expf(-f));
                v[q] = f;
            }
            const int mrow = m0 + wm + mi * 16 + r4;
            const int ncol = n0 + wn + ni * 8 + c2;
            float* p0 = out + (size_t)mrow * Cc + ncol;
            float* p1 = out + (size_t)(mrow + 8) * Cc + ncol;
            p0[0] = v[0]; p0[1] = v[1];
            p1[0] = v[2]; p1[1] = v[3];
        }
    }
}

// ---------------- base -------------------------------------------------------
__global__ __launch_bounds__(256) void base_kernel(
    const float* __restrict__ wkvstate, const float* __restrict__ tdecay,
    const float* __restrict__ faaaa, const float* __restrict__ R,
    const float* __restrict__ Kbuf, const float* __restrict__ V,
    float* __restrict__ wkv)
{
    __shared__ __align__(16) float S0s[64 * 68];
    __shared__ __align__(16) float rws[64 * 68];
    __shared__ float dotu4[64][4];
    __shared__ float dotu[64];
    __shared__ float l2w[64], us[64];

    const int bh = blockIdx.x;
    const int b = bh >> 5, h = bh & 31;
    const int t0 = blockIdx.y << 6;
    const int tid = threadIdx.x;

    if (tid < 64) {
        float e = expf(tdecay[h * 64 + tid]);
        l2w[tid] = -e * 1.4426950408889634f;
        us[tid] = faaaa[h * 64 + tid];
    }
    for (int i = tid; i < 4096; i += 256)
        S0s[(i >> 6) * 68 + (i & 63)] = wkvstate[h * 4096 + i];
    __syncthreads();

    {
        const int row = tid >> 2;
        const int kb = (tid & 3) << 4;
        const int t = t0 + row;
        const float* rp = R    + (size_t)(b * Tt + t) * Cc + h * 64;
        const float* kp = Kbuf + (size_t)(b * Tt + t) * Cc + h * 64;
        float part = 0.f;
        const float tf = (float)t;
        #pragma unroll
        for (int kk = 0; kk < 16; kk++) {
            const int k = kb + kk;
            float rv = rp[k];
            rws[row * 68 + k] = rv * exp2f(tf * l2w[k]);
            part += rv * kp[k] * us[k];
        }
        dotu4[row][tid & 3] = part;
    }
    __syncthreads();
    if (tid < 64)
        dotu[tid] = dotu4[tid][0] + dotu4[tid][1] + dotu4[tid][2] + dotu4[tid][3];
    __syncthreads();

    const int tx = tid & 15, ty = tid >> 4;
    float acc[4][4];
    #pragma unroll
    for (int i = 0; i < 4; i++)
        #pragma unroll
        for (int j = 0; j < 4; j++) acc[i][j] = 0.f;

    for (int k0 = 0; k0 < 64; k0 += 4) {
        float4 av[4], bv[4];
        #pragma unroll
        for (int i = 0; i < 4; i++)
            av[i] = *(const float4*)&rws[(ty * 4 + i) * 68 + k0];
        #pragma unroll
        for (int kk = 0; kk < 4; kk++)
            bv[kk] = *(const float4*)&S0s[(k0 + kk) * 68 + tx * 4];
        #pragma unroll
        for (int i = 0; i < 4; i++) {
            acc[i][0] += av[i].x * bv[0].x + av[i].y * bv[1].x
                       + av[i].z * bv[2].x + av[i].w * bv[3].x;
            acc[i][1] += av[i].x * bv[0].y + av[i].y * bv[1].y
                       + av[i].z * bv[2].y + av[i].w * bv[3].y;
            acc[i][2] += av[i].x * bv[0].z + av[i].y * bv[1].z
                       + av[i].z * bv[2].z + av[i].w * bv[3].z;
            acc[i][3] += av[i].x * bv[0].w + av[i].y * bv[1].w
                       + av[i].z * bv[2].w + av[i].w * bv[3].w;
        }
    }

    #pragma unroll
    for (int i = 0; i < 4; i++) {
        const int p = ty * 4 + i;
        const int t = t0 + p;
        const float* vp = V + (size_t)(b * Tt + t) * Cc + h * 64;
        const float du = dotu[p];
        float* wp = wkv + ((size_t)(b * Hh + h) * Tt + t) * 64;
        #pragma unroll
        for (int j = 0; j < 4; j++) {
            const int jn = tx * 4 + j;
            wp[jn] = acc[i][j] + du * vp[jn];
        }
    }
}

// ---------------- chunked intra scan -> g_IN (assignment, t>=1) -------------
__global__ __launch_bounds__(512) void scan_kernel(
    const float* __restrict__ tdecay,
    const float* __restrict__ R, const float* __restrict__ Kbuf,
    const float* __restrict__ V, float* __restrict__ intra)
{
    extern __shared__ float sm[];
    float* Ssm  = sm;
    float* rcs  = Ssm  + 4160;
    float* kcs  = rcs  + 4160;
    float* vcs  = kcs  + 4160;
    float* atts = vcs  + 4160;
    float* l2w  = atts + 4160;

    const int b = blockIdx.x >> 5, h = blockIdx.x & 31;
    const int tid = threadIdx.x;

    if (tid < 64)
        l2w[tid] = -expf(tdecay[h * 64 + tid]) * 1.4426950408889634f;
    for (int i = tid; i < 4160; i += 512) Ssm[i] = 0.f;
    __syncthreads();

    const int tx = tid & 15, ty = tid >> 4;
    const int lrow = tid >> 3;
    const int kb8 = (tid & 7) << 3;

    for (int ci = 0; ci < 32; ci++) {
        const int q0 = ci << 6;
        {
            const int tq = q0 + lrow;
            const int tr = tq + 1;
            const bool kvv = (tq < Tt - 1);
            const bool rvv = (tr < Tt);
            const float* rp = R    + (size_t)(b * Tt + tr) * Cc + h * 64;
            const float* kp = Kbuf + (size_t)(b * Tt + tq) * Cc + h * 64;
            const float* vp = V    + (size_t)(b * Tt + tq) * Cc + h * 64;
            const float wexp = (float)(Tt - 1 - tq);
            #pragma unroll
            for (int kk = 0; kk < 8; kk++) {
                const int k = kb8 + kk;
                rcs[lrow * 65 + k] = rvv ? rp[k] : 0.f;
                float kv = 0.f, vv = 0.f;
                if (kvv) {
                    kv = kp[k] * exp2f(wexp * l2w[k]);
                    vv = vp[k];
                }
                kcs[lrow * 65 + k] = kv;
                vcs[lrow * 65 + k] = vv;
            }
        }
        __syncthreads();

        float att[2][4], dS[2][4];
        #pragma unroll
        for (int i = 0; i < 2; i++)
            #pragma unroll
            for (int j = 0; j < 4; j++) { att[i][j] = 0.f; dS[i][j] = 0.f; }

        for (int k = 0; k < 64; k++) {
            float a[2], bb[4];
            #pragma unroll
            for (int i = 0; i < 2; i++) a[i] = rcs[(ty * 2 + i) * 65 + k];
            #pragma unroll
            for (int j = 0; j < 4; j++) bb[j] = kcs[(tx * 4 + j) * 65 + k];
            #pragma unroll
            for (int i = 0; i < 2; i++)
                #pragma unroll
                for (int j = 0; j < 4; j++) att[i][j] += a[i] * bb[j];
        }
        for (int q = 0; q < 64; q++) {
            float a[2], bb[4];
            #pragma unroll
            for (int i = 0; i < 2; i++) a[i] = kcs[q * 65 + ty * 2 + i];
            #pragma unroll
            for (int j = 0; j < 4; j++) bb[j] = vcs[q * 65 + tx * 4 + j];
            #pragma unroll
            for (int i = 0; i < 2; i++)
                #pragma unroll
                for (int j = 0; j < 4; j++) dS[i][j] += a[i] * bb[j];
        }
        #pragma unroll
        for (int i = 0; i < 2; i++)
            #pragma unroll
            for (int j = 0; j < 4; j++)
                atts[(ty * 2 + i) * 65 + tx * 4 + j] =
                    ((tx * 4 + j) <= (ty * 2 + i)) ? att[i][j] : 0.f;
        __syncthreads();

        float o[2][4];
        #pragma unroll
        for (int i = 0; i < 2; i++)
            #pragma unroll
            for (int j = 0; j < 4; j++) o[i][j] = 0.f;

        for (int q = 0; q < 64; q++) {
            float a[2], bb[4];
            #pragma unroll
            for (int i = 0; i < 2; i++) a[i] = atts[(ty * 2 + i) * 65 + q];
            #pragma unroll
            for (int j = 0; j < 4; j++) bb[j] = vcs[q * 65 + tx * 4 + j];
            #pragma unroll
            for (int i = 0; i < 2; i++)
                #pragma unroll
                for (int j = 0; j < 4; j++) o[i][j] += a[i] * bb[j];
        }
        for (int k = 0; k < 64; k++) {
            float a[2], bb[4];
            #pragma unroll
            for (int i = 0; i < 2; i++) a[i] = rcs[(ty * 2 + i) * 65 + k];
            #pragma unroll
            for (int j = 0; j < 4; j++) bb[j] = Ssm[k * 65 + tx * 4 + j];
            #pragma unroll
            for (int i = 0; i < 2; i++)
                #pragma unroll
                for (int j = 0; j < 4; j++) o[i][j] += a[i] * bb[j];
        }

        #pragma unroll
        for (int i = 0; i < 2; i++) {
            const int gt = q0 + ty * 2 + i + 1;
            if (gt < Tt) {
                float* wp = intra + ((size_t)(b * Hh + h) * Tt + gt) * 64 + tx * 4;
                #pragma unroll
                for (int j = 0; j < 4; j++) wp[j] = o[i][j];
            }
        }
        __syncthreads();

        #pragma unroll
        for (int i = 0; i < 2; i++)
            #pragma unroll
            for (int j = 0; j < 4; j++)
                Ssm[(ty * 2 + i) * 65 + tx * 4 + j] += dS[i][j];
    }
}

// ---------------- groupnorm: (wkv+intra) -> bf16 round -> gn -> gate --------
__global__ __launch_bounds__(256) void gn_kernel(
    const float* __restrict__ lnw, const float* __restrict__ lnb,
    const float* __restrict__ wkv, const float* __restrict__ intra,
    const float* __restrict__ gbuf)
{
    const int g = blockIdx.x * 8 + (threadIdx.x >> 5);
    const int lane = threadIdx.x & 31;
    const int b = g >> 16;
    const int rem = g & 65535;
    const int t = rem >> 5;
    const int h = rem & 31;

    const size_t wi = ((size_t)(b * Hh + h) * Tt + t) * 64;
    const float* wp = wkv + wi;
    const float* ip = intra + wi;
    float s0 = wp[lane];
    float s1 = wp[lane + 32];
    if (t > 0) { s0 += ip[lane]; s1 += ip[lane + 32]; }
    float v0 = __bfloat162float(__float2bfloat16(s0));
    float v1 = __bfloat162float(__float2bfloat16(s1));
    float s = v0 + v1;
    float ss = v0 * v0 + v1 * v1;
    #pragma unroll
    for (int off = 16; off; off >>= 1) {
        s  += __shfl_xor_sync(0xffffffffu, s,  off);
        ss += __shfl_xor_sync(0xffffffffu, ss, off);
    }
    const float mu  = s * (1.f / 64.f);
    const float var = ss * (1.f / 64.f) - mu * mu;
    const float inv = rsqrtf(var + EPSV);

    const int c0 = h * 64 + lane;
    const size_t gi = (size_t)(b * Tt + t) * Cc + c0;
    const float y0 = ((v0 - mu) * inv * lnw[c0]      + lnb[c0])      * gbuf[gi];
    const float y1 = ((v1 - mu) * inv * lnw[c0 + 32] + lnb[c0 + 32]) * gbuf[gi + 32];
    __half* yh = reinterpret_cast<__half*>(g_YH);
    yh[gi]      = __float2half(y0);
    yh[gi + 32] = __float2half(y1);
}

// ---------------- launch ----------------------------------------------------
extern "C" void kernel_launch(void* const* d_in, const int* in_sizes, int n_in,
                              void* d_out, int out_size)
{
    const float* x        = (const float*)d_in[0];
    const float* state    = (const float*)d_in[1];
    const float* wkvstate = (const float*)d_in[2];
    const float* tmk      = (const float*)d_in[3];
    const float* tmv      = (const float*)d_in[4];
    const float* tmr      = (const float*)d_in[5];
    const float* tmg      = (const float*)d_in[6];
    const float* tdecay   = (const float*)d_in[7];
    const float* faaaa    = (const float*)d_in[8];
    const float* w_r      = (const float*)d_in[9];
    const float* w_k      = (const float*)d_in[10];
    const float* w_v      = (const float*)d_in[11];
    const float* w_g      = (const float*)d_in[12];
    const float* w_o      = (const float*)d_in[13];
    const float* ln_w     = (const float*)d_in[14];
    const float* ln_b     = (const float*)d_in[15];
    float* out = (float*)d_out;

    float *pR, *pK, *pV, *pG, *pW, *pI;
    cudaGetSymbolAddress((void**)&pR, g_R);
    cudaGetSymbolAddress((void**)&pK, g_Kb);
    cudaGetSymbolAddress((void**)&pV, g_V);
    cudaGetSymbolAddress((void**)&pG, g_G);
    cudaGetSymbolAddress((void**)&pW, g_WKV);
    cudaGetSymbolAddress((void**)&pI, g_IN);
    __nv_bfloat16 *pAH, *pAL, *pWH, *pWL, *pYH;
    cudaGetSymbolAddress((void**)&pAH, g_AH);
    cudaGetSymbolAddress((void**)&pAL, g_AL);
    cudaGetSymbolAddress((void**)&pWH, g_WH);
    cudaGetSymbolAddress((void**)&pWL, g_WL);
    cudaGetSymbolAddress((void**)&pYH, g_YH);

    static cudaStream_t s1 = nullptr, s2 = nullptr;
    static cudaEvent_t evFork = nullptr, evW = nullptr, evMix = nullptr,
                       evRKV = nullptr, evG = nullptr, evBase = nullptr;
    if (s1 == nullptr) {
        cudaStreamCreateWithFlags(&s1, cudaStreamNonBlocking);
        cudaStreamCreateWithFlags(&s2, cudaStreamNonBlocking);
        cudaEventCreateWithFlags(&evFork, cudaEventDisableTiming);
        cudaEventCreateWithFlags(&evW,    cudaEventDisableTiming);
        cudaEventCreateWithFlags(&evMix,  cudaEventDisableTiming);
        cudaEventCreateWithFlags(&evRKV,  cudaEventDisableTiming);
        cudaEventCreateWithFlags(&evG,    cudaEventDisableTiming);
        cudaEventCreateWithFlags(&evBase, cudaEventDisableTiming);
    }

    const int scan_smem = (5 * 4160 + 64) * 4;
    cudaFuncSetAttribute(scan_kernel,
                         cudaFuncAttributeMaxDynamicSharedMemorySize, scan_smem);
    cudaFuncSetAttribute(bgemm3_kernel,
                         cudaFuncAttributeMaxDynamicSharedMemorySize, GEMM_SMEM);
    cudaFuncSetAttribute(bgemm2_kernel,
                         cudaFuncAttributeMaxDynamicSharedMemorySize, GEMM2_SMEM);

    const size_t MC = (size_t)Mm * Cc;
    const size_t CC = (size_t)Cc * Cc;

    dim3 gg(Cc / BN, Mm / BM);        // (16, 64)
    dim3 gg3(Cc / BN, Mm / BM, 3);    // (16, 64, 3)

    // fork s1 from capture-origin stream
    cudaEventRecord(evFork, 0);
    cudaStreamWaitEvent(s1, evFork, 0);

    // s1: wconv (independent of mixconv)
    wconv_kernel<<<(int)(5 * CC / 4 / 256), 256, 0, s1>>>(w_r, w_k, w_v, w_g, w_o);
    cudaEventRecord(evW, s1);

    // default: mixconv
    mixconv_kernel<<<(int)(MC / 4 / 256), 256>>>(x, state, tmr, tmk, tmv, tmg);
    cudaEventRecord(evMix, 0);

    // s1: G projection (fp16 1-term, BK=64) after mixconv done (R10 schedule)
    cudaStreamWaitEvent(s1, evMix, 0);
    bgemm2_kernel<<<gg, 256, GEMM2_SMEM, s1>>>(pAH + 3*MC, pWH + 3*CC, pG, 1);
    cudaEventRecord(evG, s1);

    // default: RKV GEMM (bf16 3-term) after wconv done
    cudaStreamWaitEvent(0, evW, 0);
    bgemm3_kernel<<<gg3, 256, GEMM_SMEM>>>(pAH, pAL, pWH, pWL, pR, pK, pV);
    cudaEventRecord(evRKV, 0);

    // s2: base overlapped with scan
    cudaStreamWaitEvent(s2, evRKV, 0);
    base_kernel<<<dim3(Bb * Hh, Tt / 64), 256, 0, s2>>>(wkvstate, tdecay, faaaa,
                                                        pR, pK, pV, pW);
    cudaEventRecord(evBase, s2);

    // default: scan
    scan_kernel<<<Bb * Hh, 512, scan_smem>>>(tdecay, pR, pK, pV, pI);

    // join for gn
    cudaStreamWaitEvent(0, evG, 0);
    cudaStreamWaitEvent(0, evBase, 0);
    gn_kernel<<<(Bb * Tt * Hh) / 8, 256>>>(ln_w, ln_b, pW, pI, pG);

    // final O projection (fp16 1-term, BK=64)
    bgemm2_kernel<<<gg, 256, GEMM2_SMEM>>>(pYH, pWH + 4*CC, out, 0);
}

// round 17
// speedup vs baseline: 1.0885x; 1.0010x over previous
#include <cuda_runtime.h>
#include <cuda_bf16.h>
#include <cuda_fp16.h>
#include <cstdint>
#include <cstddef>

// Problem constants
#define Bb 4
#define Tt 2048
#define Cc 2048
#define Hh 32
#define Kk 64
#define Mm (Bb*Tt)          // 8192
#define EPSV 0.00064f

// ---------------- scratch (device globals; no allocation allowed) ----------
__device__ __align__(256) __nv_bfloat16 g_AH[(size_t)4*Mm*Cc];
__device__ __align__(256) __nv_bfloat16 g_AL[(size_t)3*Mm*Cc];
__device__ __align__(256) __nv_bfloat16 g_WH[(size_t)5*Cc*Cc];
__device__ __align__(256) __nv_bfloat16 g_WL[(size_t)3*Cc*Cc];
__device__ __align__(256) __nv_bfloat16 g_YH[(size_t)Mm*Cc];   // fp16 payload
__device__ float g_R[(size_t)Mm*Cc];
__device__ float g_Kb[(size_t)Mm*Cc];
__device__ float g_V[(size_t)Mm*Cc];
__device__ float g_G[(size_t)Mm*Cc];
__device__ float g_WKV[(size_t)Mm*Cc];   // base term
__device__ float g_IN[(size_t)Mm*Cc];    // intra term (t>=1 valid)

// ---------------- helpers ----------------------------------------------------
__device__ __forceinline__ uint32_t smem_u32(const void* p) {
    uint32_t a;
    asm("{ .reg .u64 t; cvta.to.shared.u64 t, %1; cvt.u32.u64 %0, t; }"
        : "=r"(a) : "l"(p));
    return a;
}
#define CP16(dst, src) \
    asm volatile("cp.async.cg.shared.global [%0], [%1], 16;" :: "r"(dst), "l"(src))
#define CP_COMMIT() asm volatile("cp.async.commit_group;" ::: "memory")

__device__ __forceinline__ void ldsm4(uint32_t* r, uint32_t addr) {
    asm volatile("ldmatrix.sync.aligned.m8n8.x4.shared.b16 {%0,%1,%2,%3}, [%4];"
                 : "=r"(r[0]), "=r"(r[1]), "=r"(r[2]), "=r"(r[3]) : "r"(addr));
}
__device__ __forceinline__ void mma_bf16(float* c, const uint32_t* a,
                                         const uint32_t* b) {
    asm volatile(
        "mma.sync.aligned.m16n8k16.row.col.f32.bf16.bf16.f32 "
        "{%0,%1,%2,%3}, {%4,%5,%6,%7}, {%8,%9}, {%0,%1,%2,%3};"
        : "+f"(c[0]), "+f"(c[1]), "+f"(c[2]), "+f"(c[3])
        : "r"(a[0]), "r"(a[1]), "r"(a[2]), "r"(a[3]), "r"(b[0]), "r"(b[1]));
}
__device__ __forceinline__ void mma_fp16(float* c, const uint32_t* a,
                                         const uint32_t* b) {
    asm volatile(
        "mma.sync.aligned.m16n8k16.row.col.f32.f16.f16.f32 "
        "{%0,%1,%2,%3}, {%4,%5,%6,%7}, {%8,%9}, {%0,%1,%2,%3};"
        : "+f"(c[0]), "+f"(c[1]), "+f"(c[2]), "+f"(c[3])
        : "r"(a[0]), "r"(a[1]), "r"(a[2]), "r"(a[3]), "r"(b[0]), "r"(b[1]));
}
__device__ __forceinline__ void split2(float a, __nv_bfloat16& h, __nv_bfloat16& l) {
    h = __float2bfloat16(a);
    l = __float2bfloat16(a - __bfloat162float(h));
}

// ---------------- conversion kernels ----------------------------------------
__global__ __launch_bounds__(256) void mixconv_kernel(
    const float* __restrict__ x, const float* __restrict__ state,
    const float* __restrict__ tmr, const float* __restrict__ tmk,
    const float* __restrict__ tmv, const float* __restrict__ tmg)
{
    const size_t idx = (size_t)blockIdx.x * 256 + threadIdx.x;   // over M*C/4
    const int m = (int)(idx >> 9);
    const int c = ((int)idx & 511) << 2;
    const int t = m & (Tt - 1);

    float4 xv = *(const float4*)(x + (size_t)m * Cc + c);
    float4 pv = (t == 0) ? *(const float4*)(state + c)
                         : *(const float4*)(x + (size_t)(m - 1) * Cc + c);
    const float* tms[4] = {tmr, tmk, tmv, tmg};
    #pragma unroll
    for (int mix = 0; mix < 4; mix++) {
        float4 tv = *(const float4*)(tms[mix] + c);
        float a0 = xv.x * tv.x + pv.x * (1.f - tv.x);
        float a1 = xv.y * tv.y + pv.y * (1.f - tv.y);
        float a2 = xv.z * tv.z + pv.z * (1.f - tv.z);
        float a3 = xv.w * tv.w + pv.w * (1.f - tv.w);
        const size_t o = (size_t)mix * Mm * Cc + (size_t)m * Cc + c;
        if (mix < 3) {
            __nv_bfloat16 h[4], l[4];
            split2(a0, h[0], l[0]); split2(a1, h[1], l[1]);
            split2(a2, h[2], l[2]); split2(a3, h[3], l[3]);
            *(uint2*)(g_AH + o) = *(const uint2*)h;
            *(uint2*)(g_AL + o) = *(const uint2*)l;
        } else {
            __half h[4];
            h[0] = __float2half(a0); h[1] = __float2half(a1);
            h[2] = __float2half(a2); h[3] = __float2half(a3);
            *(uint2*)(g_AH + o) = *(const uint2*)h;
        }
    }
}

__global__ __launch_bounds__(256) void wconv_kernel(
    const float* __restrict__ w0, const float* __restrict__ w1,
    const float* __restrict__ w2, const float* __restrict__ w3,
    const float* __restrict__ w4)
{
    const size_t idx = (size_t)blockIdx.x * 256 + threadIdx.x;  // over 5*C*C/4
    const size_t per = (size_t)Cc * Cc / 4;
    const int w = (int)(idx / per);
    const size_t e4 = idx - (size_t)w * per;
    const float* ws[5] = {w0, w1, w2, w3, w4};
    float4 v = *(const float4*)(ws[w] + e4 * 4);
    const size_t o = (size_t)w * Cc * Cc + e4 * 4;
    if (w < 3) {
        __nv_bfloat16 h[4], l[4];
        split2(v.x, h[0], l[0]); split2(v.y, h[1], l[1]);
        split2(v.z, h[2], l[2]); split2(v.w, h[3], l[3]);
        *(uint2*)(g_WH + o) = *(const uint2*)h;
        *(uint2*)(g_WL + o) = *(const uint2*)l;
    } else {
        __half h[4];
        h[0] = __float2half(v.x); h[1] = __float2half(v.y);
        h[2] = __float2half(v.z); h[3] = __float2half(v.w);
        *(uint2*)(g_WH + o) = *(const uint2*)h;
    }
}

// ---------------- MODE 0: bf16 3-term GEMM (R,K,V), BK=32 --------------------
#define BM 128
#define BN 128
#define BK 32
#define STG 32768
#define GEMM_SMEM (3*STG)    // 98304

__device__ __forceinline__ void load_chunk0(
    uint32_t sbase, int stage, int kc, int m0, int n0, int tid,
    const __nv_bfloat16* Ah, const __nv_bfloat16* Al,
    const __nv_bfloat16* Bh, const __nv_bfloat16* Bl)
{
    const int k0 = kc * BK;
    const uint32_t s = sbase + stage * STG;
    #pragma unroll
    for (int p = 0; p < 2; p++) {
        const int idx = tid + p * 256;          // 0..511
        const int row = idx >> 2;
        const int ch  = idx & 3;
        const uint32_t off = (uint32_t)(row * 64 + ((ch ^ (row & 3)) << 4));
        const size_t gA = (size_t)(m0 + row) * Cc + k0 + ch * 8;
        const size_t gB = (size_t)(n0 + row) * Cc + k0 + ch * 8;
        CP16(s + off,          (const char*)(Ah + gA));
        CP16(s + 8192  + off,  (const char*)(Al + gA));
        CP16(s + 16384 + off,  (const char*)(Bh + gB));
        CP16(s + 24576 + off,  (const char*)(Bl + gB));
    }
    CP_COMMIT();
}

__device__ __forceinline__ void bgemm0_body(
    const __nv_bfloat16* __restrict__ Ah, const __nv_bfloat16* __restrict__ Al,
    const __nv_bfloat16* __restrict__ Bh, const __nv_bfloat16* __restrict__ Bl,
    float* __restrict__ out, char* smem)
{
    const uint32_t sbase = smem_u32(smem);
    const int tid = threadIdx.x;
    const int wid = tid >> 5;
    const int lane = tid & 31;
    const int m0 = blockIdx.y * BM;
    const int n0 = blockIdx.x * BN;
    const int wm = (wid & 1) * 64;
    const int wn = (wid >> 1) * 32;

    float acc[4][4][4];
    #pragma unroll
    for (int i = 0; i < 4; i++)
        #pragma unroll
        for (int j = 0; j < 4; j++)
            #pragma unroll
            for (int q = 0; q < 4; q++) acc[i][j][q] = 0.f;

    load_chunk0(sbase, 0, 0, m0, n0, tid, Ah, Al, Bh, Bl);
    load_chunk0(sbase, 1, 1, m0, n0, tid, Ah, Al, Bh, Bl);

    const int NCH = Cc / BK;   // 64
    const int tj = lane >> 3;
    const int tr = lane & 7;

    for (int i = 0; i < NCH; i++) {
        if (i < NCH - 2) asm volatile("cp.async.wait_group 1;" ::: "memory");
        else             asm volatile("cp.async.wait_group 0;" ::: "memory");
        __syncthreads();
        if (i + 2 < NCH)
            load_chunk0(sbase, (i + 2) % 3, i + 2, m0, n0, tid, Ah, Al, Bh, Bl);

        const uint32_t s = sbase + (i % 3) * STG;
        #pragma unroll
        for (int ks = 0; ks < 2; ks++) {
            uint32_t aH[4][4], aL[4][4];
            #pragma unroll
            for (int mi = 0; mi < 4; mi++) {
                const int row = wm + mi * 16 + ((tj & 1) << 3) + tr;
                const int ch = 2 * ks + (tj >> 1);
                const uint32_t off = (uint32_t)(row * 64 + ((ch ^ (row & 3)) << 4));
                ldsm4(aH[mi], s + off);
                ldsm4(aL[mi], s + 8192 + off);
            }
            uint32_t bH[4][2], bL[4][2];
            #pragma unroll
            for (int np = 0; np < 2; np++) {
                const int row = wn + np * 16 + ((tj >> 1) << 3) + tr;
                const int ch = 2 * ks + (tj & 1);
                const uint32_t off = (uint32_t)(row * 64 + ((ch ^ (row & 3)) << 4));
                uint32_t rH[4], rL[4];
                ldsm4(rH, s + 16384 + off);
                ldsm4(rL, s + 24576 + off);
                bH[np*2][0]   = rH[0]; bH[np*2][1]   = rH[1];
                bH[np*2+1][0] = rH[2]; bH[np*2+1][1] = rH[3];
                bL[np*2][0]   = rL[0]; bL[np*2][1]   = rL[1];
                bL[np*2+1][0] = rL[2]; bL[np*2+1][1] = rL[3];
            }
            #pragma unroll
            for (int mi = 0; mi < 4; mi++)
                #pragma unroll
                for (int ni = 0; ni < 4; ni++) {
                    mma_bf16(acc[mi][ni], aH[mi], bH[ni]);
                    mma_bf16(acc[mi][ni], aH[mi], bL[ni]);
                    mma_bf16(acc[mi][ni], aL[mi], bH[ni]);
                }
        }
    }

    const int r4 = lane >> 2;
    const int c2 = (lane & 3) * 2;
    #pragma unroll
    for (int mi = 0; mi < 4; mi++) {
        #pragma unroll
        for (int ni = 0; ni < 4; ni++) {
            const int mrow = m0 + wm + mi * 16 + r4;
            const int ncol = n0 + wn + ni * 8 + c2;
            float* p0 = out + (size_t)mrow * Cc + ncol;
            float* p1 = out + (size_t)(mrow + 8) * Cc + ncol;
            p0[0] = acc[mi][ni][0]; p0[1] = acc[mi][ni][1];
            p1[0] = acc[mi][ni][2]; p1[1] = acc[mi][ni][3];
        }
    }
}

__global__ __launch_bounds__(256, 2) void bgemm3_kernel(
    const __nv_bfloat16* __restrict__ AH, const __nv_bfloat16* __restrict__ AL,
    const __nv_bfloat16* __restrict__ WH, const __nv_bfloat16* __restrict__ WL,
    float* o0, float* o1, float* o2)
{
    extern __shared__ char smem[];
    const int z = blockIdx.z;
    const size_t MC = (size_t)Mm * Cc;
    const size_t CC = (size_t)Cc * Cc;
    float* out = (z == 0) ? o0 : (z == 1) ? o1 : o2;
    bgemm0_body(AH + (size_t)z * MC, AL + (size_t)z * MC,
                WH + (size_t)z * CC, WL + (size_t)z * CC, out, smem);
}

// ---------------- MODE 2: fp16 single x single GEMM (G,O), BK=64 ------------
#define BK2 64
#define STG2 32768           // A 16KB + B 16KB
#define GEMM2_SMEM (3*STG2)  // 98304

__device__ __forceinline__ void load_chunk2(
    uint32_t sbase, int stage, int kc, int m0, int n0, int tid,
    const __nv_bfloat16* Ah, const __nv_bfloat16* Bh)
{
    const int k0 = kc * BK2;
    const uint32_t s = sbase + stage * STG2;
    #pragma unroll
    for (int p = 0; p < 4; p++) {
        const int idx = tid + p * 256;          // 0..1023
        const int row = idx >> 3;               // 0..127
        const int ch  = idx & 7;
        const uint32_t off = (uint32_t)(row * 128 + ((ch ^ (row & 7)) << 4));
        const size_t gA = (size_t)(m0 + row) * Cc + k0 + ch * 8;
        const size_t gB = (size_t)(n0 + row) * Cc + k0 + ch * 8;
        CP16(s + off,         (const char*)(Ah + gA));
        CP16(s + 16384 + off, (const char*)(Bh + gB));
    }
    CP_COMMIT();
}

__global__ __launch_bounds__(256, 2) void bgemm2_kernel(
    const __nv_bfloat16* __restrict__ Ah, const __nv_bfloat16* __restrict__ Bh,
    float* __restrict__ out, int do_silu)
{
    extern __shared__ char smem[];
    const uint32_t sbase = smem_u32(smem);
    const int tid = threadIdx.x;
    const int wid = tid >> 5;
    const int lane = tid & 31;
    const int m0 = blockIdx.y * BM;
    const int n0 = blockIdx.x * BN;
    const int wm = (wid & 1) * 64;
    const int wn = (wid >> 1) * 32;

    float acc[4][4][4];
    #pragma unroll
    for (int i = 0; i < 4; i++)
        #pragma unroll
        for (int j = 0; j < 4; j++)
            #pragma unroll
            for (int q = 0; q < 4; q++) acc[i][j][q] = 0.f;

    load_chunk2(sbase, 0, 0, m0, n0, tid, Ah, Bh);
    load_chunk2(sbase, 1, 1, m0, n0, tid, Ah, Bh);

    const int NCH = Cc / BK2;   // 32
    const int tj = lane >> 3;
    const int tr = lane & 7;

    for (int i = 0; i < NCH; i++) {
        if (i < NCH - 2) asm volatile("cp.async.wait_group 1;" ::: "memory");
        else             asm volatile("cp.async.wait_group 0;" ::: "memory");
        __syncthreads();
        if (i + 2 < NCH)
            load_chunk2(sbase, (i + 2) % 3, i + 2, m0, n0, tid, Ah, Bh);

        const uint32_t s = sbase + (i % 3) * STG2;
        #pragma unroll
        for (int ks = 0; ks < 4; ks++) {
            uint32_t aH[4][4];
            #pragma unroll
            for (int mi = 0; mi < 4; mi++) {
                const int row = wm + mi * 16 + ((tj & 1) << 3) + tr;
                const int ch = 2 * ks + (tj >> 1);
                const uint32_t off = (uint32_t)(row * 128 + ((ch ^ (row & 7)) << 4));
                ldsm4(aH[mi], s + off);
            }
            uint32_t bH[4][2];
            #pragma unroll
            for (int np = 0; np < 2; np++) {
                const int row = wn + np * 16 + ((tj >> 1) << 3) + tr;
                const int ch = 2 * ks + (tj & 1);
                const uint32_t off = (uint32_t)(row * 128 + ((ch ^ (row & 7)) << 4));
                uint32_t rH[4];
                ldsm4(rH, s + 16384 + off);
                bH[np*2][0]   = rH[0]; bH[np*2][1]   = rH[1];
                bH[np*2+1][0] = rH[2]; bH[np*2+1][1] = rH[3];
            }
            #pragma unroll
            for (int mi = 0; mi < 4; mi++)
                #pragma unroll
                for (int ni = 0; ni < 4; ni++)
                    mma_fp16(acc[mi][ni], aH[mi], bH[ni]);
        }
    }

    const int r4 = lane >> 2;
    const int c2 = (lane & 3) * 2;
    #pragma unroll
    for (int mi = 0; mi < 4; mi++) {
        #pragma unroll
        for (int ni = 0; ni < 4; ni++) {
            float v[4];
            #pragma unroll
            for (int q = 0; q < 4; q++) {
                float f = acc[mi][ni][q];
                if (do_silu) f = f / (1.f + expf(-f));
                v[q] = f;
            }
            const int mrow = m0 + wm + mi * 16 + r4;
            const int ncol = n0 + wn + ni * 8 + c2;
            float* p0 = out + (size_t)mrow * Cc + ncol;
            float* p1 = out + (size_t)(mrow + 8) * Cc + ncol;
            p0[0] = v[0]; p0[1] = v[1];
            p1[0] = v[2]; p1[1] = v[3];
        }
    }
}

// ---------------- base -------------------------------------------------------
__global__ __launch_bounds__(256) void base_kernel(
    const float* __restrict__ wkvstate, const float* __restrict__ tdecay,
    const float* __restrict__ faaaa, const float* __restrict__ R,
    const float* __restrict__ Kbuf, const float* __restrict__ V,
    float* __restrict__ wkv)
{
    __shared__ __align__(16) float S0s[64 * 68];
    __shared__ __align__(16) float rws[64 * 68];
    __shared__ float dotu4[64][4];
    __shared__ float dotu[64];
    __shared__ float l2w[64], us[64];

    const int bh = blockIdx.x;
    const int b = bh >> 5, h = bh & 31;
    const int t0 = blockIdx.y << 6;
    const int tid = threadIdx.x;

    if (tid < 64) {
        float e = expf(tdecay[h * 64 + tid]);
        l2w[tid] = -e * 1.4426950408889634f;
        us[tid] = faaaa[h * 64 + tid];
    }
    for (int i = tid; i < 4096; i += 256)
        S0s[(i >> 6) * 68 + (i & 63)] = wkvstate[h * 4096 + i];
    __syncthreads();

    {
        const int row = tid >> 2;
        const int kb = (tid & 3) << 4;
        const int t = t0 + row;
        const float* rp = R    + (size_t)(b * Tt + t) * Cc + h * 64;
        const float* kp = Kbuf + (size_t)(b * Tt + t) * Cc + h * 64;
        float part = 0.f;
        const float tf = (float)t;
        #pragma unroll
        for (int kk = 0; kk < 16; kk++) {
            const int k = kb + kk;
            float rv = rp[k];
            rws[row * 68 + k] = rv * exp2f(tf * l2w[k]);
            part += rv * kp[k] * us[k];
        }
        dotu4[row][tid & 3] = part;
    }
    __syncthreads();
    if (tid < 64)
        dotu[tid] = dotu4[tid][0] + dotu4[tid][1] + dotu4[tid][2] + dotu4[tid][3];
    __syncthreads();

    const int tx = tid & 15, ty = tid >> 4;
    float acc[4][4];
    #pragma unroll
    for (int i = 0; i < 4; i++)
        #pragma unroll
        for (int j = 0; j < 4; j++) acc[i][j] = 0.f;

    for (int k0 = 0; k0 < 64; k0 += 4) {
        float4 av[4], bv[4];
        #pragma unroll
        for (int i = 0; i < 4; i++)
            av[i] = *(const float4*)&rws[(ty * 4 + i) * 68 + k0];
        #pragma unroll
        for (int kk = 0; kk < 4; kk++)
            bv[kk] = *(const float4*)&S0s[(k0 + kk) * 68 + tx * 4];
        #pragma unroll
        for (int i = 0; i < 4; i++) {
            acc[i][0] += av[i].x * bv[0].x + av[i].y * bv[1].x
                       + av[i].z * bv[2].x + av[i].w * bv[3].x;
            acc[i][1] += av[i].x * bv[0].y + av[i].y * bv[1].y
                       + av[i].z * bv[2].y + av[i].w * bv[3].y;
            acc[i][2] += av[i].x * bv[0].z + av[i].y * bv[1].z
                       + av[i].z * bv[2].z + av[i].w * bv[3].z;
            acc[i][3] += av[i].x * bv[0].w + av[i].y * bv[1].w
                       + av[i].z * bv[2].w + av[i].w * bv[3].w;
        }
    }

    #pragma unroll
    for (int i = 0; i < 4; i++) {
        const int p = ty * 4 + i;
        const int t = t0 + p;
        const float* vp = V + (size_t)(b * Tt + t) * Cc + h * 64;
        const float du = dotu[p];
        float* wp = wkv + ((size_t)(b * Hh + h) * Tt + t) * 64;
        #pragma unroll
        for (int j = 0; j < 4; j++) {
            const int jn = tx * 4 + j;
            wp[jn] = acc[i][j] + du * vp[jn];
        }
    }
}

// ---------------- chunked intra scan, register-prefetch pipelined -----------
__global__ __launch_bounds__(512) void scan_kernel(
    const float* __restrict__ tdecay,
    const float* __restrict__ R, const float* __restrict__ Kbuf,
    const float* __restrict__ V, float* __restrict__ intra)
{
    extern __shared__ float sm[];
    float* Ssm  = sm;
    float* rcs  = Ssm  + 4160;
    float* kcs  = rcs  + 4160;
    float* vcs  = kcs  + 4160;
    float* atts = vcs  + 4160;
    float* l2w  = atts + 4160;

    const int b = blockIdx.x >> 5, h = blockIdx.x & 31;
    const int tid = threadIdx.x;

    if (tid < 64)
        l2w[tid] = -expf(tdecay[h * 64 + tid]) * 1.4426950408889634f;
    for (int i = tid; i < 4160; i += 512) Ssm[i] = 0.f;
    __syncthreads();

    const int tx = tid & 15, ty = tid >> 4;
    const int lrow = tid >> 3;
    const int kb8 = (tid & 7) << 3;

    // register staging for the pipelined global loads (raw, pre-decay)
    float r_reg[8], k_reg[8], v_reg[8];

    // prefetch chunk 0
    {
        const int tq = lrow;                 // ci=0
        const int tr = tq + 1;
        const float* rp = R    + (size_t)(b * Tt + tr) * Cc + h * 64;
        const float* kp = Kbuf + (size_t)(b * Tt + tq) * Cc + h * 64;
        const float* vp = V    + (size_t)(b * Tt + tq) * Cc + h * 64;
        #pragma unroll
        for (int kk = 0; kk < 8; kk++) {
            const int k = kb8 + kk;
            r_reg[kk] = rp[k];               // tr <= 512 < Tt, valid
            k_reg[kk] = kp[k];
            v_reg[kk] = vp[k];
        }
    }

    for (int ci = 0; ci < 32; ci++) {
        const int q0 = ci << 6;
        // store staged registers into smem (apply decay to k here)
        {
            const int tq = q0 + lrow;
            const bool kvv = (tq < Tt - 1);
            const bool rvv = (tq + 1 < Tt);
            const float wexp = (float)(Tt - 1 - tq);
            #pragma unroll
            for (int kk = 0; kk < 8; kk++) {
                const int k = kb8 + kk;
                rcs[lrow * 65 + k] = rvv ? r_reg[kk] : 0.f;
                kcs[lrow * 65 + k] = kvv ? k_reg[kk] * exp2f(wexp * l2w[k]) : 0.f;
                vcs[lrow * 65 + k] = kvv ? v_reg[kk] : 0.f;
            }
        }
        __syncthreads();

        // prefetch chunk ci+1 (loads overlap the compute below)
        if (ci + 1 < 32) {
            const int tq = (ci + 1) * 64 + lrow;
            const int tr = tq + 1;
            const bool kvv = (tq < Tt - 1);
            const bool rvv = (tr < Tt);
            const float* rp = R    + (size_t)(b * Tt + (rvv ? tr : 0)) * Cc + h * 64;
            const float* kp = Kbuf + (size_t)(b * Tt + (kvv ? tq : 0)) * Cc + h * 64;
            const float* vp = V    + (size_t)(b * Tt + (kvv ? tq : 0)) * Cc + h * 64;
            #pragma unroll
            for (int kk = 0; kk < 8; kk++) {
                const int k = kb8 + kk;
                r_reg[kk] = rp[k];
                k_reg[kk] = kp[k];
                v_reg[kk] = vp[k];
            }
        }

        float att[2][4], dS[2][4];
        #pragma unroll
        for (int i = 0; i < 2; i++)
            #pragma unroll
            for (int j = 0; j < 4; j++) { att[i][j] = 0.f; dS[i][j] = 0.f; }

        for (int k = 0; k < 64; k++) {
            float a[2], bb[4];
            #pragma unroll
            for (int i = 0; i < 2; i++) a[i] = rcs[(ty * 2 + i) * 65 + k];
            #pragma unroll
            for (int j = 0; j < 4; j++) bb[j] = kcs[(tx * 4 + j) * 65 + k];
            #pragma unroll
            for (int i = 0; i < 2; i++)
                #pragma unroll
                for (int j = 0; j < 4; j++) att[i][j] += a[i] * bb[j];
        }
        for (int q = 0; q < 64; q++) {
            float a[2], bb[4];
            #pragma unroll
            for (int i = 0; i < 2; i++) a[i] = kcs[q * 65 + ty * 2 + i];
            #pragma unroll
            for (int j = 0; j < 4; j++) bb[j] = vcs[q * 65 + tx * 4 + j];
            #pragma unroll
            for (int i = 0; i < 2; i++)
                #pragma unroll
                for (int j = 0; j < 4; j++) dS[i][j] += a[i] * bb[j];
        }
        #pragma unroll
        for (int i = 0; i < 2; i++)
            #pragma unroll
            for (int j = 0; j < 4; j++)
                atts[(ty * 2 + i) * 65 + tx * 4 + j] =
                    ((tx * 4 + j) <= (ty * 2 + i)) ? att[i][j] : 0.f;
        __syncthreads();

        float o[2][4];
        #pragma unroll
        for (int i = 0; i < 2; i++)
            #pragma unroll
            for (int j = 0; j < 4; j++) o[i][j] = 0.f;

        for (int q = 0; q < 64; q++) {
            float a[2], bb[4];
            #pragma unroll
            for (int i = 0; i < 2; i++) a[i] = atts[(ty * 2 + i) * 65 + q];
            #pragma unroll
            for (int j = 0; j < 4; j++) bb[j] = vcs[q * 65 + tx * 4 + j];
            #pragma unroll
            for (int i = 0; i < 2; i++)
                #pragma unroll
                for (int j = 0; j < 4; j++) o[i][j] += a[i] * bb[j];
        }
        for (int k = 0; k < 64; k++) {
            float a[2], bb[4];
            #pragma unroll
            for (int i = 0; i < 2; i++) a[i] = rcs[(ty * 2 + i) * 65 + k];
            #pragma unroll
            for (int j = 0; j < 4; j++) bb[j] = Ssm[k * 65 + tx * 4 + j];
            #pragma unroll
            for (int i = 0; i < 2; i++)
                #pragma unroll
                for (int j = 0; j < 4; j++) o[i][j] += a[i] * bb[j];
        }

        #pragma unroll
        for (int i = 0; i < 2; i++) {
            const int gt = q0 + ty * 2 + i + 1;
            if (gt < Tt) {
                float* wp = intra + ((size_t)(b * Hh + h) * Tt + gt) * 64 + tx * 4;
                #pragma unroll
                for (int j = 0; j < 4; j++) wp[j] = o[i][j];
            }
        }
        __syncthreads();

        #pragma unroll
        for (int i = 0; i < 2; i++)
            #pragma unroll
            for (int j = 0; j < 4; j++)
                Ssm[(ty * 2 + i) * 65 + tx * 4 + j] += dS[i][j];
    }
}

// ---------------- groupnorm: (wkv+intra) -> bf16 round -> gn -> gate --------
__global__ __launch_bounds__(256) void gn_kernel(
    const float* __restrict__ lnw, const float* __restrict__ lnb,
    const float* __restrict__ wkv, const float* __restrict__ intra,
    const float* __restrict__ gbuf)
{
    const int g = blockIdx.x * 8 + (threadIdx.x >> 5);
    const int lane = threadIdx.x & 31;
    const int b = g >> 16;
    const int rem = g & 65535;
    const int t = rem >> 5;
    const int h = rem & 31;

    const size_t wi = ((size_t)(b * Hh + h) * Tt + t) * 64;
    const float* wp = wkv + wi;
    const float* ip = intra + wi;
    float s0 = wp[lane];
    float s1 = wp[lane + 32];
    if (t > 0) { s0 += ip[lane]; s1 += ip[lane + 32]; }
    float v0 = __bfloat162float(__float2bfloat16(s0));
    float v1 = __bfloat162float(__float2bfloat16(s1));
    float s = v0 + v1;
    float ss = v0 * v0 + v1 * v1;
    #pragma unroll
    for (int off = 16; off; off >>= 1) {
        s  += __shfl_xor_sync(0xffffffffu, s,  off);
        ss += __shfl_xor_sync(0xffffffffu, ss, off);
    }
    const float mu  = s * (1.f / 64.f);
    const float var = ss * (1.f / 64.f) - mu * mu;
    const float inv = rsqrtf(var + EPSV);

    const int c0 = h * 64 + lane;
    const size_t gi = (size_t)(b * Tt + t) * Cc + c0;
    const float y0 = ((v0 - mu) * inv * lnw[c0]      + lnb[c0])      * gbuf[gi];
    const float y1 = ((v1 - mu) * inv * lnw[c0 + 32] + lnb[c0 + 32]) * gbuf[gi + 32];
    __half* yh = reinterpret_cast<__half*>(g_YH);
    yh[gi]      = __float2half(y0);
    yh[gi + 32] = __float2half(y1);
}

// ---------------- launch ----------------------------------------------------
extern "C" void kernel_launch(void* const* d_in, const int* in_sizes, int n_in,
                              void* d_out, int out_size)
{
    const float* x        = (const float*)d_in[0];
    const float* state    = (const float*)d_in[1];
    const float* wkvstate = (const float*)d_in[2];
    const float* tmk      = (const float*)d_in[3];
    const float* tmv      = (const float*)d_in[4];
    const float* tmr      = (const float*)d_in[5];
    const float* tmg      = (const float*)d_in[6];
    const float* tdecay   = (const float*)d_in[7];
    const float* faaaa    = (const float*)d_in[8];
    const float* w_r      = (const float*)d_in[9];
    const float* w_k      = (const float*)d_in[10];
    const float* w_v      = (const float*)d_in[11];
    const float* w_g      = (const float*)d_in[12];
    const float* w_o      = (const float*)d_in[13];
    const float* ln_w     = (const float*)d_in[14];
    const float* ln_b     = (const float*)d_in[15];
    float* out = (float*)d_out;

    float *pR, *pK, *pV, *pG, *pW, *pI;
    cudaGetSymbolAddress((void**)&pR, g_R);
    cudaGetSymbolAddress((void**)&pK, g_Kb);
    cudaGetSymbolAddress((void**)&pV, g_V);
    cudaGetSymbolAddress((void**)&pG, g_G);
    cudaGetSymbolAddress((void**)&pW, g_WKV);
    cudaGetSymbolAddress((void**)&pI, g_IN);
    __nv_bfloat16 *pAH, *pAL, *pWH, *pWL, *pYH;
    cudaGetSymbolAddress((void**)&pAH, g_AH);
    cudaGetSymbolAddress((void**)&pAL, g_AL);
    cudaGetSymbolAddress((void**)&pWH, g_WH);
    cudaGetSymbolAddress((void**)&pWL, g_WL);
    cudaGetSymbolAddress((void**)&pYH, g_YH);

    static cudaStream_t s1 = nullptr, s2 = nullptr;
    static cudaEvent_t evFork = nullptr, evW = nullptr, evMix = nullptr,
                       evRKV = nullptr, evG = nullptr, evBase = nullptr;
    if (s1 == nullptr) {
        cudaStreamCreateWithFlags(&s1, cudaStreamNonBlocking);
        cudaStreamCreateWithFlags(&s2, cudaStreamNonBlocking);
        cudaEventCreateWithFlags(&evFork, cudaEventDisableTiming);
        cudaEventCreateWithFlags(&evW,    cudaEventDisableTiming);
        cudaEventCreateWithFlags(&evMix,  cudaEventDisableTiming);
        cudaEventCreateWithFlags(&evRKV,  cudaEventDisableTiming);
        cudaEventCreateWithFlags(&evG,    cudaEventDisableTiming);
        cudaEventCreateWithFlags(&evBase, cudaEventDisableTiming);
    }

    const int scan_smem = (5 * 4160 + 64) * 4;
    cudaFuncSetAttribute(scan_kernel,
                         cudaFuncAttributeMaxDynamicSharedMemorySize, scan_smem);
    cudaFuncSetAttribute(bgemm3_kernel,
                         cudaFuncAttributeMaxDynamicSharedMemorySize, GEMM_SMEM);
    cudaFuncSetAttribute(bgemm2_kernel,
                         cudaFuncAttributeMaxDynamicSharedMemorySize, GEMM2_SMEM);

    const size_t MC = (size_t)Mm * Cc;
    const size_t CC = (size_t)Cc * Cc;

    dim3 gg(Cc / BN, Mm / BM);        // (16, 64)
    dim3 gg3(Cc / BN, Mm / BM, 3);    // (16, 64, 3)

    // fork s1 from capture-origin stream
    cudaEventRecord(evFork, 0);
    cudaStreamWaitEvent(s1, evFork, 0);

    // s1: wconv (independent of mixconv)
    wconv_kernel<<<(int)(5 * CC / 4 / 256), 256, 0, s1>>>(w_r, w_k, w_v, w_g, w_o);
    cudaEventRecord(evW, s1);

    // default: mixconv
    mixconv_kernel<<<(int)(MC / 4 / 256), 256>>>(x, state, tmr, tmk, tmv, tmg);
    cudaEventRecord(evMix, 0);

    // s1: G projection (fp16 1-term, BK=64) after mixconv done
    cudaStreamWaitEvent(s1, evMix, 0);
    bgemm2_kernel<<<gg, 256, GEMM2_SMEM, s1>>>(pAH + 3*MC, pWH + 3*CC, pG, 1);
    cudaEventRecord(evG, s1);

    // default: RKV GEMM (bf16 3-term) after wconv done
    cudaStreamWaitEvent(0, evW, 0);
    bgemm3_kernel<<<gg3, 256, GEMM_SMEM>>>(pAH, pAL, pWH, pWL, pR, pK, pV);
    cudaEventRecord(evRKV, 0);

    // s2: base overlapped with scan
    cudaStreamWaitEvent(s2, evRKV, 0);
    base_kernel<<<dim3(Bb * Hh, Tt / 64), 256, 0, s2>>>(wkvstate, tdecay, faaaa,
                                                        pR, pK, pV, pW);
    cudaEventRecord(evBase, s2);

    // default: scan (register-prefetch pipelined)
    scan_kernel<<<Bb * Hh, 512, scan_smem>>>(tdecay, pR, pK, pV, pI);

    // join for gn
    cudaStreamWaitEvent(0, evG, 0);
    cudaStreamWaitEvent(0, evBase, 0);
    gn_kernel<<<(Bb * Tt * Hh) / 8, 256>>>(ln_w, ln_b, pW, pI, pG);

    // final O projection (fp16 1-term, BK=64)
    bgemm2_kernel<<<gg, 256, GEMM2_SMEM>>>(pYH, pWH + 4*CC, out, 0);
}